// round 14
// baseline (speedup 1.0000x reference)
#include <cuda_runtime.h>
#include <cuda_bf16.h>
#include <cuda_fp16.h>
#include <math.h>
#include <stdint.h>

#define BATCH 2
#define SEQ   2048
#define HID   1024
#define NH    16
#define HD    64
#define MTOT  (BATCH*SEQ)
#define OUT_ELEMS   (MTOT*HID)
#define W_ELEMS     (BATCH*NH*SEQ*SEQ)
#define KS2   2048               /* f16 split-K: [hi(32) | lo(32)] x 1024 */
#define LOG2E 1.44269504088896340736f

/* ---------------- scratch (no allocations allowed) ---------------- */
__device__ float g_cos[SEQ*(HD/2)];
__device__ float g_sin[SEQ*(HD/2)];

__device__ __half g_Qh[BATCH*NH*SEQ*HD];
__device__ __half g_Ql[BATCH*NH*SEQ*HD];
__device__ __half g_Kh[BATCH*NH*SEQ*HD];
__device__ __half g_Vh[BATCH*NH*SEQ*HD];

__device__ __half s_q [MTOT*KS2];
__device__ __half s_k [MTOT*KS2];
__device__ __half s_v [MTOT*1024];
__device__ __half s_at[MTOT*KS2];
__device__ __half s_wq[HID*KS2];
__device__ __half s_wk[HID*KS2];
__device__ __half s_wv[HID*1024];
__device__ __half s_wo[HID*KS2];

/* ---------------- helpers ---------------- */
__device__ __forceinline__ uint32_t smem_u32(const void* p) {
    uint32_t a;
    asm("{ .reg .u64 t; cvta.to.shared.u64 t, %1; cvt.u32.u64 %0, t; }"
        : "=r"(a) : "l"(p));
    return a;
}
__device__ __forceinline__ void cp16(uint32_t s, const void* g) {
    asm volatile("cp.async.cg.shared.global [%0], [%1], 16;"
                 :: "r"(s), "l"(g));
}
#define CP_COMMIT() asm volatile("cp.async.commit_group;" ::: "memory")
#define CP_WAIT(N)  asm volatile("cp.async.wait_group %0;" :: "n"(N) : "memory")

__device__ __forceinline__ void ldsm4(uint32_t& r0, uint32_t& r1,
                                      uint32_t& r2, uint32_t& r3, uint32_t addr)
{
    asm volatile("ldmatrix.sync.aligned.m8n8.x4.shared.b16 {%0,%1,%2,%3}, [%4];"
                 : "=r"(r0), "=r"(r1), "=r"(r2), "=r"(r3) : "r"(addr));
}
__device__ __forceinline__ void ldsm4t(uint32_t& r0, uint32_t& r1,
                                       uint32_t& r2, uint32_t& r3, uint32_t addr)
{
    asm volatile("ldmatrix.sync.aligned.m8n8.x4.trans.shared.b16 {%0,%1,%2,%3}, [%4];"
                 : "=r"(r0), "=r"(r1), "=r"(r2), "=r"(r3) : "r"(addr));
}
__device__ __forceinline__ void mma_f16(float* d, const uint32_t* a,
                                        uint32_t b0, uint32_t b1)
{
    asm volatile(
        "mma.sync.aligned.m16n8k16.row.col.f32.f16.f16.f32 "
        "{%0,%1,%2,%3}, {%4,%5,%6,%7}, {%8,%9}, {%0,%1,%2,%3};"
        : "+f"(d[0]), "+f"(d[1]), "+f"(d[2]), "+f"(d[3])
        : "r"(a[0]), "r"(a[1]), "r"(a[2]), "r"(a[3]), "r"(b0), "r"(b1));
}
__device__ __forceinline__ float ex2(float x) {
    float y;
    asm("ex2.approx.ftz.f32 %0, %1;" : "=f"(y) : "f"(x));
    return y;
}
__device__ __forceinline__ uint32_t pack_h2(float x, float y) {
    __half2 t = __floats2half2_rn(x, y);
    return *(uint32_t*)&t;
}

/* ------ merged fp32 -> f16 split + RoPE tables, one launch -------- */
__global__ void __launch_bounds__(256)
split_all(const float* __restrict__ q, const float* __restrict__ k,
          const float* __restrict__ v, const float* __restrict__ Wq,
          const float* __restrict__ Wk, const float* __restrict__ Wv,
          const float* __restrict__ Wo)
{
    int bid = blockIdx.x;
    int tid = threadIdx.x;

    if (bid >= 32768) {                    /* rope tables */
        int idx = ((bid - 32768) << 8) + tid;
        int s = idx >> 5, j = idx & 31;
        double inv = exp(-((double)(2*j) / (double)HD) * log(10000.0));
        double ang = (double)s * inv;
        g_cos[idx] = (float)cos(ang);
        g_sin[idx] = (float)sin(ang);
        return;
    }

    if (bid < 16384) {                     /* q, k: A-format split */
        int t = bid >> 13;
        const float* src = t ? k : q;
        __half* dst = t ? s_k : s_q;
        int idx2 = ((bid & 8191) << 8) + tid;
        float2 x = ((const float2*)src)[idx2];
        int row = idx2 >> 9, kk = (idx2 & 511) * 2;
        int blk = kk >> 5,  j  = kk & 31;
        __half2 hi = __floats2half2_rn(x.x, x.y);
        size_t base = (size_t)row * KS2 + blk*64 + j;
        *(__half2*)(dst + base) = hi;
        *(__half2*)(dst + base + 32) = __floats2half2_rn(
            x.x - __half2float(hi.x), x.y - __half2float(hi.y));
        return;
    }
    if (bid < 24576) {                     /* v: flat f16 */
        int idx2 = ((bid - 16384) << 8) + tid;
        float2 x = ((const float2*)v)[idx2];
        *(__half2*)(s_v + (size_t)idx2*2) = __floats2half2_rn(x.x, x.y);
        return;
    }
    if (bid < 30720) {                     /* Wq, Wk, Wo: B-format */
        int r = bid - 24576;
        int t = r >> 11;
        const float* src = (t == 0) ? Wq : (t == 1) ? Wk : Wo;
        __half* dst = (t == 0) ? s_wq : (t == 1) ? s_wk : s_wo;
        int idx2 = ((r & 2047) << 8) + tid;
        float2 x = ((const float2*)src)[idx2];
        int row = idx2 >> 9, kk = (idx2 & 511) * 2;
        int blk = kk >> 5,  j  = kk & 31;
        __half2 hi = __floats2half2_rn(x.x, x.y);
        size_t base = (size_t)row * KS2 + blk*64 + j;
        *(__half2*)(dst + base)      = hi;
        *(__half2*)(dst + base + 32) = hi;
        return;
    }
    {                                      /* Wv: flat f16 */
        int idx2 = ((bid - 30720) << 8) + tid;
        float2 x = ((const float2*)Wv)[idx2];
        *(__half2*)(s_wv + (size_t)idx2*2) = __floats2half2_rn(x.x, x.y);
    }
}

/* ================= GEMM mainloop core (f16) ================= */
#define GSTG 36864

template<int KSZ>
__device__ __forceinline__ void gemm_core(
    const __half* __restrict__ A, const __half* __restrict__ B,
    char* gsm, int tid, int warp_m, int warp_n, int l,
    int m0, int n0, float acc[2][8][4])
{
    const uint32_t sb = smem_u32(gsm);
    const uint4* gA = (const uint4*)(A + (size_t)m0 * KSZ);
    const uint4* gB = (const uint4*)(B + (size_t)n0 * KSZ);

    uint32_t a_off[2], b_off[4];
#pragma unroll
    for (int mt = 0; mt < 2; mt++)
        a_off[mt] = (warp_m*32 + mt*16 + (l & 15))*144 + (l >> 4)*16;
#pragma unroll
    for (int nt = 0; nt < 4; nt++) {
        int row = warp_n*64 + nt*16 + (l & 7) + ((l >> 4) & 1) * 8;
        b_off[nt] = 18432 + row*144 + ((l >> 3) & 1)*16;
    }

    auto load_stage = [&](int stg, int it) {
        uint32_t base = sb + stg*GSTG;
#pragma unroll
        for (int u = 0; u < 4; u++) {
            int f = u*256 + tid;
            int r = f >> 3, c = f & 7;
            cp16(base + r*144 + c*16,         gA + (size_t)r*(KSZ/8) + it*8 + c);
            cp16(base + 18432 + r*144 + c*16, gB + (size_t)r*(KSZ/8) + it*8 + c);
        }
    };

    load_stage(0, 0);
    CP_COMMIT();

    for (int it = 0; it < KSZ/64; it++) {
        int cur = it & 1;
        if (it + 1 < KSZ/64) {
            load_stage(cur ^ 1, it + 1);
            CP_COMMIT();
            CP_WAIT(1);
        } else {
            CP_WAIT(0);
        }
        __syncthreads();

        uint32_t stgb = sb + cur*GSTG;
#pragma unroll
        for (int ks = 0; ks < 4; ks++) {
            uint32_t a[2][4], b[4][4];
#pragma unroll
            for (int mt = 0; mt < 2; mt++)
                ldsm4(a[mt][0], a[mt][1], a[mt][2], a[mt][3],
                      stgb + a_off[mt] + ks*32);
#pragma unroll
            for (int nt = 0; nt < 4; nt++)
                ldsm4(b[nt][0], b[nt][1], b[nt][2], b[nt][3],
                      stgb + b_off[nt] + ks*32);
#pragma unroll
            for (int mt = 0; mt < 2; mt++)
#pragma unroll
                for (int nt = 0; nt < 4; nt++) {
                    mma_f16(acc[mt][nt*2],   a[mt], b[nt][0], b[nt][1]);
                    mma_f16(acc[mt][nt*2+1], a[mt], b[nt][2], b[nt][3]);
                }
        }
        __syncthreads();
    }
}

/* ---- merged QKV projection GEMM: z = 0 (Q), 1 (K), 2 (V) ---- */
__global__ void __launch_bounds__(256, 2)
gemm_qkv(const float* __restrict__ bq, const float* __restrict__ bk,
         const float* __restrict__ bv)
{
    extern __shared__ __align__(16) char gsm[];

    const int tid = threadIdx.x;
    const int wid = tid >> 5, l = tid & 31;
    const int warp_m = wid >> 1, warp_n = wid & 1;
    const int m0 = blockIdx.y * 128;
    const int n0 = blockIdx.x * 128;
    const int z = blockIdx.z;

    const float* bias = (z == 0) ? bq : (z == 1) ? bk : bv;

    float acc[2][8][4];
#pragma unroll
    for (int i = 0; i < 2; i++)
#pragma unroll
        for (int j = 0; j < 8; j++)
#pragma unroll
            for (int p = 0; p < 4; p++) acc[i][j][p] = 0.f;

    if (z == 2)
        gemm_core<1024>(s_v, s_wv, gsm, tid, warp_m, warp_n, l, m0, n0, acc);
    else
        gemm_core<2048>((z == 0) ? s_q : s_k, (z == 0) ? s_wq : s_wk,
                        gsm, tid, warp_m, warp_n, l, m0, n0, acc);

    const int g = l >> 2, q = l & 3;
#pragma unroll
    for (int mt = 0; mt < 2; mt++) {
        int mrow0 = m0 + warp_m*32 + mt*16 + g;
#pragma unroll
        for (int nt2 = 0; nt2 < 8; nt2++) {
            int ncol = n0 + warp_n*64 + nt2*8 + q*2;
            float b0 = bias[ncol], b1 = bias[ncol+1];
            float c0 = acc[mt][nt2][0] + b0;
            float c1 = acc[mt][nt2][1] + b1;
            float c2 = acc[mt][nt2][2] + b0;
            float c3 = acc[mt][nt2][3] + b1;

            int h = ncol >> 6, d = ncol & 63;
            int bb0 = mrow0 >> 11, ss0 = mrow0 & 2047;
            int mrow1 = mrow0 + 8;
            int bb1 = mrow1 >> 11, ss1 = mrow1 & 2047;
            if (z < 2) {
                float cs0 = g_cos[ss0*32 + (d>>1)], sn0 = g_sin[ss0*32 + (d>>1)];
                float cs1 = g_cos[ss1*32 + (d>>1)], sn1 = g_sin[ss1*32 + (d>>1)];
                float t0 = c0*cs0 - c1*sn0, t1 = c0*sn0 + c1*cs0;
                float t2 = c2*cs1 - c3*sn1, t3 = c2*sn1 + c3*cs1;
                c0 = t0; c1 = t1; c2 = t2; c3 = t3;
            }
            size_t a0 = (((size_t)(bb0*NH + h)*SEQ + ss0) << 6) + d;
            size_t a1 = (((size_t)(bb1*NH + h)*SEQ + ss1) << 6) + d;
            __half h0 = __float2half_rn(c0);
            __half h1 = __float2half_rn(c1);
            __half h2 = __float2half_rn(c2);
            __half h3 = __float2half_rn(c3);
            if (z == 0) {
                *(__half2*)(g_Qh + a0) = __halves2half2(h0, h1);
                *(__half2*)(g_Qh + a1) = __halves2half2(h2, h3);
                *(__half2*)(g_Ql + a0) = __floats2half2_rn(
                    c0 - __half2float(h0), c1 - __half2float(h1));
                *(__half2*)(g_Ql + a1) = __floats2half2_rn(
                    c2 - __half2float(h2), c3 - __half2float(h3));
            } else if (z == 1) {
                *(__half2*)(g_Kh + a0) = __halves2half2(h0, h1);
                *(__half2*)(g_Kh + a1) = __halves2half2(h2, h3);
            } else {
                *(__half2*)(g_Vh + a0) = __halves2half2(h0, h1);
                *(__half2*)(g_Vh + a1) = __halves2half2(h2, h3);
            }
        }
    }
}

/* ---- output projection GEMM with interleaved zero-fill ---- */
__global__ void __launch_bounds__(256, 2)
gemm_out(const float* __restrict__ bo, float* __restrict__ dst,
         float* __restrict__ wout, int write_w)
{
    extern __shared__ __align__(16) char gsm[];

    const int tid = threadIdx.x;
    const int wid = tid >> 5, l = tid & 31;
    const int warp_m = wid >> 1, warp_n = wid & 1;
    const int m0 = blockIdx.y * 128;
    const int n0 = blockIdx.x * 128;
    const uint32_t sb = smem_u32(gsm);

    /* zero-fill assignment: CTA c handles (bh,qt) pairs c and 511-c */
    const int cpair = blockIdx.y * 8 + blockIdx.x;

    const uint4* gA = (const uint4*)(s_at + (size_t)m0 * KS2);
    const uint4* gB = (const uint4*)(s_wo + (size_t)n0 * KS2);

    float acc[2][8][4];
#pragma unroll
    for (int i = 0; i < 2; i++)
#pragma unroll
        for (int j = 0; j < 8; j++)
#pragma unroll
            for (int p = 0; p < 4; p++) acc[i][j][p] = 0.f;

    uint32_t a_off[2], b_off[4];
#pragma unroll
    for (int mt = 0; mt < 2; mt++)
        a_off[mt] = (warp_m*32 + mt*16 + (l & 15))*144 + (l >> 4)*16;
#pragma unroll
    for (int nt = 0; nt < 4; nt++) {
        int row = warp_n*64 + nt*16 + (l & 7) + ((l >> 4) & 1) * 8;
        b_off[nt] = 18432 + row*144 + ((l >> 3) & 1)*16;
    }

    auto load_stage = [&](int stg, int it) {
        uint32_t base = sb + stg*GSTG;
#pragma unroll
        for (int u = 0; u < 4; u++) {
            int f = u*256 + tid;
            int r = f >> 3, c = f & 7;
            cp16(base + r*144 + c*16,         gA + (size_t)r*256 + it*8 + c);
            cp16(base + 18432 + r*144 + c*16, gB + (size_t)r*256 + it*8 + c);
        }
    };

    load_stage(0, 0);
    CP_COMMIT();

    for (int it = 0; it < 32; it++) {
        int cur = it & 1;
        if (it + 1 < 32) {
            load_stage(cur ^ 1, it + 1);
            CP_COMMIT();
            CP_WAIT(1);
        } else {
            CP_WAIT(0);
        }
        __syncthreads();

        /* interleaved zero-fill: 4 rows per pair per iteration */
        if (write_w) {
            float4 z4 = make_float4(0.f, 0.f, 0.f, 0.f);
#pragma unroll
            for (int u = 0; u < 2; u++) {
                int p = u ? (511 - cpair) : cpair;
                int bh = p >> 4, qt = p & 15;
                int nf4 = (15 - qt) * 32;
                if (nf4 > 0) {
                    int q0 = qt * 128;
                    float* basep = wout + ((size_t)bh*SEQ + q0 + it*4)*SEQ
                                        + q0 + 128;
                    for (int r = 0; r < 4; r++) {
                        float4* rowp = (float4*)(basep + (size_t)r*SEQ);
                        for (int c4 = tid; c4 < nf4; c4 += 256)
                            __stcs(rowp + c4, z4);
                    }
                }
            }
        }

        uint32_t stgb = sb + cur*GSTG;
#pragma unroll
        for (int ks = 0; ks < 4; ks++) {
            uint32_t a[2][4], b[4][4];
#pragma unroll
            for (int mt = 0; mt < 2; mt++)
                ldsm4(a[mt][0], a[mt][1], a[mt][2], a[mt][3],
                      stgb + a_off[mt] + ks*32);
#pragma unroll
            for (int nt = 0; nt < 4; nt++)
                ldsm4(b[nt][0], b[nt][1], b[nt][2], b[nt][3],
                      stgb + b_off[nt] + ks*32);
#pragma unroll
            for (int mt = 0; mt < 2; mt++)
#pragma unroll
                for (int nt = 0; nt < 4; nt++) {
                    mma_f16(acc[mt][nt*2],   a[mt], b[nt][0], b[nt][1]);
                    mma_f16(acc[mt][nt*2+1], a[mt], b[nt][2], b[nt][3]);
                }
        }
        __syncthreads();
    }

    const int g = l >> 2, q = l & 3;
#pragma unroll
    for (int mt = 0; mt < 2; mt++) {
        int mrow0 = m0 + warp_m*32 + mt*16 + g;
#pragma unroll
        for (int nt2 = 0; nt2 < 8; nt2++) {
            int ncol = n0 + warp_n*64 + nt2*8 + q*2;
            float b0 = bo[ncol], b1 = bo[ncol+1];
            *(float2*)(dst + (size_t)mrow0    *HID + ncol) =
                make_float2(acc[mt][nt2][0] + b0, acc[mt][nt2][1] + b1);
            *(float2*)(dst + (size_t)(mrow0+8)*HID + ncol) =
                make_float2(acc[mt][nt2][2] + b0, acc[mt][nt2][3] + b1);
        }
    }
}

/* ================= two-pass attention, causal-paired, f16 =========
   Pass 1: 3-stage pipeline (K only), 1 barrier/tile.
   Pass 2: 2-stage K/V + fp32 smem weight staging -> coalesced stores. */
#define QSZ   36864
#define ASTG  18432
#define WSTG_OFF (QSZ + 2*ASTG)            /* 73728 */
#define ASMEM (WSTG_OFF + 128*68*4)        /* 108544 */

__global__ void __launch_bounds__(256, 2)
attn_mma(float* __restrict__ wout, int write_w)
{
    extern __shared__ __align__(16) char dsm[];
    float* smW = (float*)(dsm + WSTG_OFF);
    const int tid = threadIdx.x;
    const int w = tid >> 5, l = tid & 31;
    const int g = l >> 2, q = l & 3;
    const int h = blockIdx.y, b = blockIdx.z;
    const size_t basebh = (size_t)(b*NH + h) * SEQ;
    const uint32_t sb = smem_u32(dsm);
    const float CE = 0.125f * LOG2E;

    uint32_t bk_off[4];
    {
        int krow = (l & 7) + ((l >> 4) & 1) * 8;
        int kcb  = ((l >> 3) & 1) * 16;
#pragma unroll
        for (int nt = 0; nt < 4; nt++)
            bk_off[nt] = (nt*16 + krow)*144 + kcb;
    }
    const uint32_t aQh = sb + (w*16 + (l & 15))*144 + (l >> 4)*16;
    const uint32_t aQl = aQh + 18432;
    const uint32_t av_off = 9216 + (l & 15)*144 + (l >> 4)*16;
    const int rloc0 = w*16 + g, rloc1 = rloc0 + 8;

    auto loadK = [&](int stg, int kb) {
        uint32_t base = sb + QSZ + stg*ASTG;
        const uint4* gkh = (const uint4*)(g_Kh + (basebh + kb*64) * HD);
#pragma unroll
        for (int u = 0; u < 2; u++) {
            int f = u*256 + tid;
            int r = f >> 3, c = f & 7;
            cp16(base + r*144 + c*16, gkh + r*8 + c);
        }
    };
    auto loadKV = [&](int stg, int kb) {
        uint32_t base = sb + QSZ + stg*ASTG;
        const uint4* gkh = (const uint4*)(g_Kh + (basebh + kb*64) * HD);
        const uint4* gvh = (const uint4*)(g_Vh + (basebh + kb*64) * HD);
#pragma unroll
        for (int u = 0; u < 2; u++) {
            int f = u*256 + tid;
            int r = f >> 3, c = f & 7;
            cp16(base + r*144 + c*16,        gkh + r*8 + c);
            cp16(base + 9216 + r*144 + c*16, gvh + r*8 + c);
        }
    };

    auto qk_tile = [&](uint32_t kbase, float acc[8][4]) {
#pragma unroll
        for (int nt = 0; nt < 8; nt++)
#pragma unroll
            for (int p = 0; p < 4; p++) acc[nt][p] = 0.f;
#pragma unroll
        for (int ks = 0; ks < 4; ks++) {
            uint32_t ah[4], al[4];
            ldsm4(ah[0], ah[1], ah[2], ah[3], aQh + ks*32);
            ldsm4(al[0], al[1], al[2], al[3], aQl + ks*32);
#pragma unroll
            for (int np = 0; np < 4; np++) {
                uint32_t kh[4];
                ldsm4(kh[0], kh[1], kh[2], kh[3], kbase + bk_off[np] + ks*32);
                mma_f16(acc[np*2],   ah, kh[0], kh[1]);
                mma_f16(acc[np*2+1], ah, kh[2], kh[3]);
                mma_f16(acc[np*2],   al, kh[0], kh[1]);
                mma_f16(acc[np*2+1], al, kh[2], kh[3]);
            }
        }
    };

    for (int half = 0; half < 2; half++) {
        const int qt = half ? blockIdx.x : (15 - blockIdx.x);
        const int q0 = qt * 128;
        const int nkt = 2*qt + 2;
        const int rw0 = q0 + w*16;
        const int r0 = rw0 + g, r1 = r0 + 8;

        /* Q loads */
        {
            const uint4* gh = (const uint4*)(g_Qh + (basebh + q0) * HD);
            const uint4* gl = (const uint4*)(g_Ql + (basebh + q0) * HD);
#pragma unroll
            for (int u = 0; u < 4; u++) {
                int f = u*256 + tid;
                int r = f >> 3, c = f & 7;
                cp16(sb + r*144 + c*16,         gh + r*8 + c);
                cp16(sb + 18432 + r*144 + c*16, gl + r*8 + c);
            }
            CP_COMMIT();
        }

        float m2[2] = {-1e30f, -1e30f};
        float l2[2] = {0.f, 0.f};

        /* ---------------- PASS 1: row max & sum (3-stage) -------- */
        loadK(0, 0);
        CP_COMMIT();
        if (nkt > 1) { loadK(1, 1); CP_COMMIT(); }

        for (int kb = 0; kb < nkt; kb++) {
            if (kb + 1 < nkt) CP_WAIT(1); else CP_WAIT(0);
            __syncthreads();
            if (kb + 2 < nkt) {
                loadK((kb + 2) % 3, kb + 2);
                CP_COMMIT();
            }

            float acc[8][4];
            qk_tile(sb + QSZ + (kb % 3)*ASTG, acc);

            const bool needmask = (kb*64 + 63) > rw0;
#pragma unroll
            for (int nt = 0; nt < 8; nt++) {
                int k0c = kb*64 + nt*8 + q*2;
                acc[nt][0] = (!needmask || k0c   <= r0) ? acc[nt][0]*CE : -1e30f;
                acc[nt][1] = (!needmask || k0c+1 <= r0) ? acc[nt][1]*CE : -1e30f;
                acc[nt][2] = (!needmask || k0c   <= r1) ? acc[nt][2]*CE : -1e30f;
                acc[nt][3] = (!needmask || k0c+1 <= r1) ? acc[nt][3]*CE : -1e30f;
            }
            float tm0 = -1e30f, tm1 = -1e30f;
#pragma unroll
            for (int nt = 0; nt < 8; nt++) {
                tm0 = fmaxf(tm0, fmaxf(acc[nt][0], acc[nt][1]));
                tm1 = fmaxf(tm1, fmaxf(acc[nt][2], acc[nt][3]));
            }
            tm0 = fmaxf(tm0, __shfl_xor_sync(0xffffffffu, tm0, 1));
            tm0 = fmaxf(tm0, __shfl_xor_sync(0xffffffffu, tm0, 2));
            tm1 = fmaxf(tm1, __shfl_xor_sync(0xffffffffu, tm1, 1));
            tm1 = fmaxf(tm1, __shfl_xor_sync(0xffffffffu, tm1, 2));
            float mn0 = fmaxf(m2[0], tm0), mn1 = fmaxf(m2[1], tm1);
            float s0 = 0.f, s1 = 0.f;
#pragma unroll
            for (int nt = 0; nt < 8; nt++) {
                s0 += ex2(acc[nt][0] - mn0) + ex2(acc[nt][1] - mn0);
                s1 += ex2(acc[nt][2] - mn1) + ex2(acc[nt][3] - mn1);
            }
            s0 += __shfl_xor_sync(0xffffffffu, s0, 1);
            s0 += __shfl_xor_sync(0xffffffffu, s0, 2);
            s1 += __shfl_xor_sync(0xffffffffu, s1, 1);
            s1 += __shfl_xor_sync(0xffffffffu, s1, 2);
            l2[0] = l2[0] * ex2(m2[0] - mn0) + s0;  m2[0] = mn0;
            l2[1] = l2[1] * ex2(m2[1] - mn1) + s1;  m2[1] = mn1;
        }

        const float invl0 = 1.f / l2[0];
        const float invl1 = 1.f / l2[1];

        float o[8][4];
#pragma unroll
        for (int nd = 0; nd < 8; nd++)
#pragma unroll
            for (int p = 0; p < 4; p++) o[nd][p] = 0.f;

        /* ---------------- PASS 2 (2-stage + smem weight staging) -- */
        __syncthreads();
        loadKV(0, 0);
        CP_COMMIT();

        for (int kb = 0; kb < nkt; kb++) {
            CP_WAIT(0);
            __syncthreads();     /* stage kb ready; smW free; old stage free */
            if (kb + 1 < nkt) {
                loadKV((kb + 1) & 1, kb + 1);
                CP_COMMIT();
            }

            uint32_t kbase = sb + QSZ + (kb & 1)*ASTG;
            float acc[8][4];
            qk_tile(kbase, acc);

            const bool needmask = (kb*64 + 63) > rw0;
            uint32_t ew0[8], ew1[8];
#pragma unroll
            for (int nt = 0; nt < 8; nt++) {
                int k0c = kb*64 + nt*8 + q*2;
                float w0 = (!needmask || k0c   <= r0)
                           ? ex2(acc[nt][0]*CE - m2[0]) * invl0 : 0.f;
                float w1 = (!needmask || k0c+1 <= r0)
                           ? ex2(acc[nt][1]*CE - m2[0]) * invl0 : 0.f;
                float w2 = (!needmask || k0c   <= r1)
                           ? ex2(acc[nt][2]*CE - m2[1]) * invl1 : 0.f;
                float w3 = (!needmask || k0c+1 <= r1)
                           ? ex2(acc[nt][3]*CE - m2[1]) * invl1 : 0.f;
                ew0[nt] = pack_h2(w0, w1);
                ew1[nt] = pack_h2(w2, w3);
                if (write_w) {
                    int cc = nt*8 + q*2;
                    *(float2*)(smW + rloc0*68 + cc) = make_float2(w0, w1);
                    *(float2*)(smW + rloc1*68 + cc) = make_float2(w2, w3);
                }
            }

            /* PV: w exact-f16 x vh */
#pragma unroll
            for (int t = 0; t < 4; t++) {
                uint32_t aw[4] = {ew0[2*t], ew1[2*t], ew0[2*t+1], ew1[2*t+1]};
#pragma unroll
                for (int nd = 0; nd < 4; nd++) {
                    uint32_t vh[4];
                    ldsm4t(vh[0], vh[1], vh[2], vh[3],
                           kbase + av_off + t*2304 + nd*32);
                    mma_f16(o[nd*2],   aw, vh[0], vh[1]);
                    mma_f16(o[nd*2+1], aw, vh[2], vh[3]);
                }
            }

            __syncthreads();     /* smW complete */
            if (write_w) {       /* coalesced readout: 128x64 fp32 tile */
                int r = tid >> 1, halfc = (tid & 1) * 32;
                const float* srow = smW + r*68 + halfc;
                float* drow = wout + (basebh + q0 + r)*SEQ + kb*64 + halfc;
#pragma unroll
                for (int i = 0; i < 8; i++)
                    __stcs((float4*)drow + i, *(const float4*)(srow + i*4));
            }
        }

        /* write O in f16 split-A format for the out-projection */
        {
            size_t mg0 = (size_t)b*SEQ + q0 + w*16 + g;
            size_t mg1 = mg0 + 8;
#pragma unroll
            for (int nd = 0; nd < 8; nd++) {
                int col = h*64 + nd*8 + q*2;
                int blk = col >> 5, j = col & 31;
                size_t b0 = mg0*KS2 + blk*64 + j;
                size_t b1 = mg1*KS2 + blk*64 + j;
                float c0 = o[nd][0], c1 = o[nd][1];
                float c2 = o[nd][2], c3 = o[nd][3];
                __half h0 = __float2half_rn(c0);
                __half h1 = __float2half_rn(c1);
                __half h2 = __float2half_rn(c2);
                __half h3 = __float2half_rn(c3);
                *(__half2*)(s_at + b0)      = __halves2half2(h0, h1);
                *(__half2*)(s_at + b0 + 32) = __floats2half2_rn(
                    c0 - __half2float(h0), c1 - __half2float(h1));
                *(__half2*)(s_at + b1)      = __halves2half2(h2, h3);
                *(__half2*)(s_at + b1 + 32) = __floats2half2_rn(
                    c2 - __half2float(h2), c3 - __half2float(h3));
            }
        }
        __syncthreads();
    }
}

/* ---------------- launcher ---------------- */
extern "C" void kernel_launch(void* const* d_in, const int* in_sizes, int n_in,
                              void* d_out, int out_size)
{
    const float* q  = (const float*)d_in[0];
    const float* k  = (const float*)d_in[1];
    const float* v  = (const float*)d_in[2];
    const float* Wq = (const float*)d_in[3];
    const float* bq = (const float*)d_in[4];
    const float* Wk = (const float*)d_in[5];
    const float* bk = (const float*)d_in[6];
    const float* Wv = (const float*)d_in[7];
    const float* bv = (const float*)d_in[8];
    const float* Wo = (const float*)d_in[9];
    const float* bo = (const float*)d_in[10];

    float* out  = (float*)d_out;
    int write_w = (out_size >= OUT_ELEMS + W_ELEMS) ? 1 : 0;
    float* wout = out + OUT_ELEMS;

    split_all<<<33024, 256>>>(q, k, v, Wq, Wk, Wv, Wo);

    cudaFuncSetAttribute(gemm_qkv,
                         cudaFuncAttributeMaxDynamicSharedMemorySize, 2*GSTG);
    cudaFuncSetAttribute(gemm_out,
                         cudaFuncAttributeMaxDynamicSharedMemorySize, 2*GSTG);
    cudaFuncSetAttribute(attn_mma,
                         cudaFuncAttributeMaxDynamicSharedMemorySize, ASMEM);

    gemm_qkv<<<dim3(HID/128, MTOT/128, 3), 256, 2*GSTG>>>(bq, bk, bv);

    attn_mma<<<dim3(8, NH, BATCH), 256, ASMEM>>>(wout, write_w);

    gemm_out<<<dim3(HID/128, MTOT/128), 256, 2*GSTG>>>(bo, out, wout, write_w);
}

// round 15
// speedup vs baseline: 1.1982x; 1.1982x over previous
#include <cuda_runtime.h>
#include <cuda_bf16.h>
#include <cuda_fp16.h>
#include <math.h>
#include <stdint.h>

#define BATCH 2
#define SEQ   2048
#define HID   1024
#define NH    16
#define HD    64
#define MTOT  (BATCH*SEQ)
#define OUT_ELEMS   (MTOT*HID)
#define W_ELEMS     (BATCH*NH*SEQ*SEQ)
#define KS2   2048               /* f16 split-K: [hi(32) | lo(32)] x 1024 */
#define LOG2E 1.44269504088896340736f

/* ---------------- scratch (no allocations allowed) ---------------- */
__device__ float g_cos[SEQ*(HD/2)];
__device__ float g_sin[SEQ*(HD/2)];

__device__ __half g_Qh[BATCH*NH*SEQ*HD];
__device__ __half g_Ql[BATCH*NH*SEQ*HD];
__device__ __half g_Kh[BATCH*NH*SEQ*HD];
__device__ __half g_Vh[BATCH*NH*SEQ*HD];

__device__ __half s_q [MTOT*KS2];
__device__ __half s_k [MTOT*KS2];
__device__ __half s_v [MTOT*1024];
__device__ __half s_at[MTOT*KS2];
__device__ __half s_wq[HID*KS2];
__device__ __half s_wk[HID*KS2];
__device__ __half s_wv[HID*1024];
__device__ __half s_wo[HID*KS2];

/* ---------------- helpers ---------------- */
__device__ __forceinline__ uint32_t smem_u32(const void* p) {
    uint32_t a;
    asm("{ .reg .u64 t; cvta.to.shared.u64 t, %1; cvt.u32.u64 %0, t; }"
        : "=r"(a) : "l"(p));
    return a;
}
__device__ __forceinline__ void cp16(uint32_t s, const void* g) {
    asm volatile("cp.async.cg.shared.global [%0], [%1], 16;"
                 :: "r"(s), "l"(g));
}
#define CP_COMMIT() asm volatile("cp.async.commit_group;" ::: "memory")
#define CP_WAIT(N)  asm volatile("cp.async.wait_group %0;" :: "n"(N) : "memory")

__device__ __forceinline__ void ldsm4(uint32_t& r0, uint32_t& r1,
                                      uint32_t& r2, uint32_t& r3, uint32_t addr)
{
    asm volatile("ldmatrix.sync.aligned.m8n8.x4.shared.b16 {%0,%1,%2,%3}, [%4];"
                 : "=r"(r0), "=r"(r1), "=r"(r2), "=r"(r3) : "r"(addr));
}
__device__ __forceinline__ void ldsm4t(uint32_t& r0, uint32_t& r1,
                                       uint32_t& r2, uint32_t& r3, uint32_t addr)
{
    asm volatile("ldmatrix.sync.aligned.m8n8.x4.trans.shared.b16 {%0,%1,%2,%3}, [%4];"
                 : "=r"(r0), "=r"(r1), "=r"(r2), "=r"(r3) : "r"(addr));
}
__device__ __forceinline__ void mma_f16(float* d, const uint32_t* a,
                                        uint32_t b0, uint32_t b1)
{
    asm volatile(
        "mma.sync.aligned.m16n8k16.row.col.f32.f16.f16.f32 "
        "{%0,%1,%2,%3}, {%4,%5,%6,%7}, {%8,%9}, {%0,%1,%2,%3};"
        : "+f"(d[0]), "+f"(d[1]), "+f"(d[2]), "+f"(d[3])
        : "r"(a[0]), "r"(a[1]), "r"(a[2]), "r"(a[3]), "r"(b0), "r"(b1));
}
__device__ __forceinline__ float ex2(float x) {
    float y;
    asm("ex2.approx.ftz.f32 %0, %1;" : "=f"(y) : "f"(x));
    return y;
}
__device__ __forceinline__ uint32_t pack_h2(float x, float y) {
    __half2 t = __floats2half2_rn(x, y);
    return *(uint32_t*)&t;
}

/* ------ merged fp32 -> f16 split + RoPE tables, one launch -------- */
__global__ void __launch_bounds__(256)
split_all(const float* __restrict__ q, const float* __restrict__ k,
          const float* __restrict__ v, const float* __restrict__ Wq,
          const float* __restrict__ Wk, const float* __restrict__ Wv,
          const float* __restrict__ Wo)
{
    int bid = blockIdx.x;
    int tid = threadIdx.x;

    if (bid >= 32768) {                    /* rope tables */
        int idx = ((bid - 32768) << 8) + tid;
        int s = idx >> 5, j = idx & 31;
        double inv = exp(-((double)(2*j) / (double)HD) * log(10000.0));
        double ang = (double)s * inv;
        g_cos[idx] = (float)cos(ang);
        g_sin[idx] = (float)sin(ang);
        return;
    }

    if (bid < 16384) {                     /* q, k: A-format split */
        int t = bid >> 13;
        const float* src = t ? k : q;
        __half* dst = t ? s_k : s_q;
        int idx2 = ((bid & 8191) << 8) + tid;
        float2 x = ((const float2*)src)[idx2];
        int row = idx2 >> 9, kk = (idx2 & 511) * 2;
        int blk = kk >> 5,  j  = kk & 31;
        __half2 hi = __floats2half2_rn(x.x, x.y);
        size_t base = (size_t)row * KS2 + blk*64 + j;
        *(__half2*)(dst + base) = hi;
        *(__half2*)(dst + base + 32) = __floats2half2_rn(
            x.x - __half2float(hi.x), x.y - __half2float(hi.y));
        return;
    }
    if (bid < 24576) {                     /* v: flat f16 */
        int idx2 = ((bid - 16384) << 8) + tid;
        float2 x = ((const float2*)v)[idx2];
        *(__half2*)(s_v + (size_t)idx2*2) = __floats2half2_rn(x.x, x.y);
        return;
    }
    if (bid < 30720) {                     /* Wq, Wk, Wo: B-format */
        int r = bid - 24576;
        int t = r >> 11;
        const float* src = (t == 0) ? Wq : (t == 1) ? Wk : Wo;
        __half* dst = (t == 0) ? s_wq : (t == 1) ? s_wk : s_wo;
        int idx2 = ((r & 2047) << 8) + tid;
        float2 x = ((const float2*)src)[idx2];
        int row = idx2 >> 9, kk = (idx2 & 511) * 2;
        int blk = kk >> 5,  j  = kk & 31;
        __half2 hi = __floats2half2_rn(x.x, x.y);
        size_t base = (size_t)row * KS2 + blk*64 + j;
        *(__half2*)(dst + base)      = hi;
        *(__half2*)(dst + base + 32) = hi;
        return;
    }
    {                                      /* Wv: flat f16 */
        int idx2 = ((bid - 30720) << 8) + tid;
        float2 x = ((const float2*)Wv)[idx2];
        *(__half2*)(s_wv + (size_t)idx2*2) = __floats2half2_rn(x.x, x.y);
    }
}

/* ================= GEMM mainloop core (f16) ================= */
#define GSTG 36864

template<int KSZ>
__device__ __forceinline__ void gemm_core(
    const __half* __restrict__ A, const __half* __restrict__ B,
    char* gsm, int tid, int warp_m, int warp_n, int l,
    int m0, int n0, float acc[2][8][4])
{
    const uint32_t sb = smem_u32(gsm);
    const uint4* gA = (const uint4*)(A + (size_t)m0 * KSZ);
    const uint4* gB = (const uint4*)(B + (size_t)n0 * KSZ);

    uint32_t a_off[2], b_off[4];
#pragma unroll
    for (int mt = 0; mt < 2; mt++)
        a_off[mt] = (warp_m*32 + mt*16 + (l & 15))*144 + (l >> 4)*16;
#pragma unroll
    for (int nt = 0; nt < 4; nt++) {
        int row = warp_n*64 + nt*16 + (l & 7) + ((l >> 4) & 1) * 8;
        b_off[nt] = 18432 + row*144 + ((l >> 3) & 1)*16;
    }

    auto load_stage = [&](int stg, int it) {
        uint32_t base = sb + stg*GSTG;
#pragma unroll
        for (int u = 0; u < 4; u++) {
            int f = u*256 + tid;
            int r = f >> 3, c = f & 7;
            cp16(base + r*144 + c*16,         gA + (size_t)r*(KSZ/8) + it*8 + c);
            cp16(base + 18432 + r*144 + c*16, gB + (size_t)r*(KSZ/8) + it*8 + c);
        }
    };

    load_stage(0, 0);
    CP_COMMIT();

    for (int it = 0; it < KSZ/64; it++) {
        int cur = it & 1;
        if (it + 1 < KSZ/64) {
            load_stage(cur ^ 1, it + 1);
            CP_COMMIT();
            CP_WAIT(1);
        } else {
            CP_WAIT(0);
        }
        __syncthreads();

        uint32_t stgb = sb + cur*GSTG;
#pragma unroll
        for (int ks = 0; ks < 4; ks++) {
            uint32_t a[2][4], b[4][4];
#pragma unroll
            for (int mt = 0; mt < 2; mt++)
                ldsm4(a[mt][0], a[mt][1], a[mt][2], a[mt][3],
                      stgb + a_off[mt] + ks*32);
#pragma unroll
            for (int nt = 0; nt < 4; nt++)
                ldsm4(b[nt][0], b[nt][1], b[nt][2], b[nt][3],
                      stgb + b_off[nt] + ks*32);
#pragma unroll
            for (int mt = 0; mt < 2; mt++)
#pragma unroll
                for (int nt = 0; nt < 4; nt++) {
                    mma_f16(acc[mt][nt*2],   a[mt], b[nt][0], b[nt][1]);
                    mma_f16(acc[mt][nt*2+1], a[mt], b[nt][2], b[nt][3]);
                }
        }
        __syncthreads();
    }
}

/* ---- merged QKV projection GEMM: z = 0 (Q), 1 (K), 2 (V) ---- */
__global__ void __launch_bounds__(256, 2)
gemm_qkv(const float* __restrict__ bq, const float* __restrict__ bk,
         const float* __restrict__ bv)
{
    extern __shared__ __align__(16) char gsm[];

    const int tid = threadIdx.x;
    const int wid = tid >> 5, l = tid & 31;
    const int warp_m = wid >> 1, warp_n = wid & 1;
    const int m0 = blockIdx.y * 128;
    const int n0 = blockIdx.x * 128;
    const int z = blockIdx.z;

    const float* bias = (z == 0) ? bq : (z == 1) ? bk : bv;

    float acc[2][8][4];
#pragma unroll
    for (int i = 0; i < 2; i++)
#pragma unroll
        for (int j = 0; j < 8; j++)
#pragma unroll
            for (int p = 0; p < 4; p++) acc[i][j][p] = 0.f;

    if (z == 2)
        gemm_core<1024>(s_v, s_wv, gsm, tid, warp_m, warp_n, l, m0, n0, acc);
    else
        gemm_core<2048>((z == 0) ? s_q : s_k, (z == 0) ? s_wq : s_wk,
                        gsm, tid, warp_m, warp_n, l, m0, n0, acc);

    const int g = l >> 2, q = l & 3;
#pragma unroll
    for (int mt = 0; mt < 2; mt++) {
        int mrow0 = m0 + warp_m*32 + mt*16 + g;
#pragma unroll
        for (int nt2 = 0; nt2 < 8; nt2++) {
            int ncol = n0 + warp_n*64 + nt2*8 + q*2;
            float b0 = bias[ncol], b1 = bias[ncol+1];
            float c0 = acc[mt][nt2][0] + b0;
            float c1 = acc[mt][nt2][1] + b1;
            float c2 = acc[mt][nt2][2] + b0;
            float c3 = acc[mt][nt2][3] + b1;

            int h = ncol >> 6, d = ncol & 63;
            int bb0 = mrow0 >> 11, ss0 = mrow0 & 2047;
            int mrow1 = mrow0 + 8;
            int bb1 = mrow1 >> 11, ss1 = mrow1 & 2047;
            if (z < 2) {
                float cs0 = g_cos[ss0*32 + (d>>1)], sn0 = g_sin[ss0*32 + (d>>1)];
                float cs1 = g_cos[ss1*32 + (d>>1)], sn1 = g_sin[ss1*32 + (d>>1)];
                float t0 = c0*cs0 - c1*sn0, t1 = c0*sn0 + c1*cs0;
                float t2 = c2*cs1 - c3*sn1, t3 = c2*sn1 + c3*cs1;
                c0 = t0; c1 = t1; c2 = t2; c3 = t3;
            }
            size_t a0 = (((size_t)(bb0*NH + h)*SEQ + ss0) << 6) + d;
            size_t a1 = (((size_t)(bb1*NH + h)*SEQ + ss1) << 6) + d;
            __half h0 = __float2half_rn(c0);
            __half h1 = __float2half_rn(c1);
            __half h2 = __float2half_rn(c2);
            __half h3 = __float2half_rn(c3);
            if (z == 0) {
                *(__half2*)(g_Qh + a0) = __halves2half2(h0, h1);
                *(__half2*)(g_Qh + a1) = __halves2half2(h2, h3);
                *(__half2*)(g_Ql + a0) = __floats2half2_rn(
                    c0 - __half2float(h0), c1 - __half2float(h1));
                *(__half2*)(g_Ql + a1) = __floats2half2_rn(
                    c2 - __half2float(h2), c3 - __half2float(h3));
            } else if (z == 1) {
                *(__half2*)(g_Kh + a0) = __halves2half2(h0, h1);
                *(__half2*)(g_Kh + a1) = __halves2half2(h2, h3);
            } else {
                *(__half2*)(g_Vh + a0) = __halves2half2(h0, h1);
                *(__half2*)(g_Vh + a1) = __halves2half2(h2, h3);
            }
        }
    }
}

/* ---- output projection GEMM with interleaved zero-fill ---- */
__global__ void __launch_bounds__(256, 2)
gemm_out(const float* __restrict__ bo, float* __restrict__ dst,
         float* __restrict__ wout, int write_w)
{
    extern __shared__ __align__(16) char gsm[];

    const int tid = threadIdx.x;
    const int wid = tid >> 5, l = tid & 31;
    const int warp_m = wid >> 1, warp_n = wid & 1;
    const int m0 = blockIdx.y * 128;
    const int n0 = blockIdx.x * 128;
    const uint32_t sb = smem_u32(gsm);

    const int cpair = blockIdx.y * 8 + blockIdx.x;

    const uint4* gA = (const uint4*)(s_at + (size_t)m0 * KS2);
    const uint4* gB = (const uint4*)(s_wo + (size_t)n0 * KS2);

    float acc[2][8][4];
#pragma unroll
    for (int i = 0; i < 2; i++)
#pragma unroll
        for (int j = 0; j < 8; j++)
#pragma unroll
            for (int p = 0; p < 4; p++) acc[i][j][p] = 0.f;

    uint32_t a_off[2], b_off[4];
#pragma unroll
    for (int mt = 0; mt < 2; mt++)
        a_off[mt] = (warp_m*32 + mt*16 + (l & 15))*144 + (l >> 4)*16;
#pragma unroll
    for (int nt = 0; nt < 4; nt++) {
        int row = warp_n*64 + nt*16 + (l & 7) + ((l >> 4) & 1) * 8;
        b_off[nt] = 18432 + row*144 + ((l >> 3) & 1)*16;
    }

    auto load_stage = [&](int stg, int it) {
        uint32_t base = sb + stg*GSTG;
#pragma unroll
        for (int u = 0; u < 4; u++) {
            int f = u*256 + tid;
            int r = f >> 3, c = f & 7;
            cp16(base + r*144 + c*16,         gA + (size_t)r*256 + it*8 + c);
            cp16(base + 18432 + r*144 + c*16, gB + (size_t)r*256 + it*8 + c);
        }
    };

    load_stage(0, 0);
    CP_COMMIT();

    for (int it = 0; it < 32; it++) {
        int cur = it & 1;
        if (it + 1 < 32) {
            load_stage(cur ^ 1, it + 1);
            CP_COMMIT();
            CP_WAIT(1);
        } else {
            CP_WAIT(0);
        }
        __syncthreads();

        /* interleaved zero-fill: 4 rows per pair per iteration */
        if (write_w) {
            float4 z4 = make_float4(0.f, 0.f, 0.f, 0.f);
#pragma unroll
            for (int u = 0; u < 2; u++) {
                int p = u ? (511 - cpair) : cpair;
                int bh = p >> 4, qt = p & 15;
                int nf4 = (15 - qt) * 32;
                if (nf4 > 0) {
                    int q0 = qt * 128;
                    float* basep = wout + ((size_t)bh*SEQ + q0 + it*4)*SEQ
                                        + q0 + 128;
                    for (int r = 0; r < 4; r++) {
                        float4* rowp = (float4*)(basep + (size_t)r*SEQ);
                        for (int c4 = tid; c4 < nf4; c4 += 256)
                            __stcs(rowp + c4, z4);
                    }
                }
            }
        }

        uint32_t stgb = sb + cur*GSTG;
#pragma unroll
        for (int ks = 0; ks < 4; ks++) {
            uint32_t a[2][4], b[4][4];
#pragma unroll
            for (int mt = 0; mt < 2; mt++)
                ldsm4(a[mt][0], a[mt][1], a[mt][2], a[mt][3],
                      stgb + a_off[mt] + ks*32);
#pragma unroll
            for (int nt = 0; nt < 4; nt++)
                ldsm4(b[nt][0], b[nt][1], b[nt][2], b[nt][3],
                      stgb + b_off[nt] + ks*32);
#pragma unroll
            for (int mt = 0; mt < 2; mt++)
#pragma unroll
                for (int nt = 0; nt < 4; nt++) {
                    mma_f16(acc[mt][nt*2],   a[mt], b[nt][0], b[nt][1]);
                    mma_f16(acc[mt][nt*2+1], a[mt], b[nt][2], b[nt][3]);
                }
        }
        __syncthreads();
    }

    const int g = l >> 2, q = l & 3;
#pragma unroll
    for (int mt = 0; mt < 2; mt++) {
        int mrow0 = m0 + warp_m*32 + mt*16 + g;
#pragma unroll
        for (int nt2 = 0; nt2 < 8; nt2++) {
            int ncol = n0 + warp_n*64 + nt2*8 + q*2;
            float b0 = bo[ncol], b1 = bo[ncol+1];
            *(float2*)(dst + (size_t)mrow0    *HID + ncol) =
                make_float2(acc[mt][nt2][0] + b0, acc[mt][nt2][1] + b1);
            *(float2*)(dst + (size_t)(mrow0+8)*HID + ncol) =
                make_float2(acc[mt][nt2][2] + b0, acc[mt][nt2][3] + b1);
        }
    }
}

/* ================= two-pass attention, causal-paired, f16 (R13) ==== */
#define QSZ   36864
#define ASTG  18432
#define ASMEM (QSZ + 3*ASTG)

__global__ void __launch_bounds__(256, 2)
attn_mma(float* __restrict__ wout, int write_w)
{
    extern __shared__ __align__(16) char dsm[];
    const int tid = threadIdx.x;
    const int w = tid >> 5, l = tid & 31;
    const int g = l >> 2, q = l & 3;
    const int h = blockIdx.y, b = blockIdx.z;
    const size_t basebh = (size_t)(b*NH + h) * SEQ;
    const uint32_t sb = smem_u32(dsm);
    const float CE = 0.125f * LOG2E;

    uint32_t bk_off[4];
    {
        int krow = (l & 7) + ((l >> 4) & 1) * 8;
        int kcb  = ((l >> 3) & 1) * 16;
#pragma unroll
        for (int nt = 0; nt < 4; nt++)
            bk_off[nt] = (nt*16 + krow)*144 + kcb;
    }
    const uint32_t aQh = sb + (w*16 + (l & 15))*144 + (l >> 4)*16;
    const uint32_t aQl = aQh + 18432;
    const uint32_t av_off = 9216 + (l & 15)*144 + (l >> 4)*16;

    auto loadK = [&](int stg, int kb) {
        uint32_t base = sb + QSZ + stg*ASTG;
        const uint4* gkh = (const uint4*)(g_Kh + (basebh + kb*64) * HD);
#pragma unroll
        for (int u = 0; u < 2; u++) {
            int f = u*256 + tid;
            int r = f >> 3, c = f & 7;
            cp16(base + r*144 + c*16, gkh + r*8 + c);
        }
    };
    auto loadKV = [&](int stg, int kb) {
        uint32_t base = sb + QSZ + stg*ASTG;
        const uint4* gkh = (const uint4*)(g_Kh + (basebh + kb*64) * HD);
        const uint4* gvh = (const uint4*)(g_Vh + (basebh + kb*64) * HD);
#pragma unroll
        for (int u = 0; u < 2; u++) {
            int f = u*256 + tid;
            int r = f >> 3, c = f & 7;
            cp16(base + r*144 + c*16,        gkh + r*8 + c);
            cp16(base + 9216 + r*144 + c*16, gvh + r*8 + c);
        }
    };

    auto qk_tile = [&](uint32_t kbase, float acc[8][4]) {
#pragma unroll
        for (int nt = 0; nt < 8; nt++)
#pragma unroll
            for (int p = 0; p < 4; p++) acc[nt][p] = 0.f;
#pragma unroll
        for (int ks = 0; ks < 4; ks++) {
            uint32_t ah[4], al[4];
            ldsm4(ah[0], ah[1], ah[2], ah[3], aQh + ks*32);
            ldsm4(al[0], al[1], al[2], al[3], aQl + ks*32);
#pragma unroll
            for (int np = 0; np < 4; np++) {
                uint32_t kh[4];
                ldsm4(kh[0], kh[1], kh[2], kh[3], kbase + bk_off[np] + ks*32);
                mma_f16(acc[np*2],   ah, kh[0], kh[1]);
                mma_f16(acc[np*2+1], ah, kh[2], kh[3]);
                mma_f16(acc[np*2],   al, kh[0], kh[1]);
                mma_f16(acc[np*2+1], al, kh[2], kh[3]);
            }
        }
    };

    for (int half = 0; half < 2; half++) {
        const int qt = half ? blockIdx.x : (15 - blockIdx.x);
        const int q0 = qt * 128;
        const int nkt = 2*qt + 2;
        const int rw0 = q0 + w*16;
        const int r0 = rw0 + g, r1 = r0 + 8;

        /* Q loads */
        {
            const uint4* gh = (const uint4*)(g_Qh + (basebh + q0) * HD);
            const uint4* gl = (const uint4*)(g_Ql + (basebh + q0) * HD);
#pragma unroll
            for (int u = 0; u < 4; u++) {
                int f = u*256 + tid;
                int r = f >> 3, c = f & 7;
                cp16(sb + r*144 + c*16,         gh + r*8 + c);
                cp16(sb + 18432 + r*144 + c*16, gl + r*8 + c);
            }
            CP_COMMIT();
        }

        float m2[2] = {-1e30f, -1e30f};
        float l2[2] = {0.f, 0.f};

        /* ---------------- PASS 1: row max & sum ---------------- */
        loadK(0, 0);
        CP_COMMIT();
        if (nkt > 1) { loadK(1, 1); CP_COMMIT(); }

        for (int kb = 0; kb < nkt; kb++) {
            if (kb + 1 < nkt) CP_WAIT(1); else CP_WAIT(0);
            __syncthreads();
            if (kb + 2 < nkt) {
                loadK((kb + 2) % 3, kb + 2);
                CP_COMMIT();
            }

            float acc[8][4];
            qk_tile(sb + QSZ + (kb % 3)*ASTG, acc);

            const bool needmask = (kb*64 + 63) > rw0;
#pragma unroll
            for (int nt = 0; nt < 8; nt++) {
                int k0c = kb*64 + nt*8 + q*2;
                acc[nt][0] = (!needmask || k0c   <= r0) ? acc[nt][0]*CE : -1e30f;
                acc[nt][1] = (!needmask || k0c+1 <= r0) ? acc[nt][1]*CE : -1e30f;
                acc[nt][2] = (!needmask || k0c   <= r1) ? acc[nt][2]*CE : -1e30f;
                acc[nt][3] = (!needmask || k0c+1 <= r1) ? acc[nt][3]*CE : -1e30f;
            }
            float tm0 = -1e30f, tm1 = -1e30f;
#pragma unroll
            for (int nt = 0; nt < 8; nt++) {
                tm0 = fmaxf(tm0, fmaxf(acc[nt][0], acc[nt][1]));
                tm1 = fmaxf(tm1, fmaxf(acc[nt][2], acc[nt][3]));
            }
            tm0 = fmaxf(tm0, __shfl_xor_sync(0xffffffffu, tm0, 1));
            tm0 = fmaxf(tm0, __shfl_xor_sync(0xffffffffu, tm0, 2));
            tm1 = fmaxf(tm1, __shfl_xor_sync(0xffffffffu, tm1, 1));
            tm1 = fmaxf(tm1, __shfl_xor_sync(0xffffffffu, tm1, 2));
            float mn0 = fmaxf(m2[0], tm0), mn1 = fmaxf(m2[1], tm1);
            float s0 = 0.f, s1 = 0.f;
#pragma unroll
            for (int nt = 0; nt < 8; nt++) {
                s0 += ex2(acc[nt][0] - mn0) + ex2(acc[nt][1] - mn0);
                s1 += ex2(acc[nt][2] - mn1) + ex2(acc[nt][3] - mn1);
            }
            s0 += __shfl_xor_sync(0xffffffffu, s0, 1);
            s0 += __shfl_xor_sync(0xffffffffu, s0, 2);
            s1 += __shfl_xor_sync(0xffffffffu, s1, 1);
            s1 += __shfl_xor_sync(0xffffffffu, s1, 2);
            l2[0] = l2[0] * ex2(m2[0] - mn0) + s0;  m2[0] = mn0;
            l2[1] = l2[1] * ex2(m2[1] - mn1) + s1;  m2[1] = mn1;
        }

        const float invl0 = 1.f / l2[0];
        const float invl1 = 1.f / l2[1];

        float o[8][4];
#pragma unroll
        for (int nd = 0; nd < 8; nd++)
#pragma unroll
            for (int p = 0; p < 4; p++) o[nd][p] = 0.f;

        /* ---------------- PASS 2: weights + O ---------------- */
        __syncthreads();
        loadKV(0, 0);
        CP_COMMIT();
        if (nkt > 1) { loadKV(1, 1); CP_COMMIT(); }

        for (int kb = 0; kb < nkt; kb++) {
            if (kb + 1 < nkt) CP_WAIT(1); else CP_WAIT(0);
            __syncthreads();
            if (kb + 2 < nkt) {
                loadKV((kb + 2) % 3, kb + 2);
                CP_COMMIT();
            }

            uint32_t kbase = sb + QSZ + (kb % 3)*ASTG;
            float acc[8][4];
            qk_tile(kbase, acc);

            const bool needmask = (kb*64 + 63) > rw0;
            uint32_t ew0[8], ew1[8];
#pragma unroll
            for (int nt = 0; nt < 8; nt++) {
                int k0c = kb*64 + nt*8 + q*2;
                float w0 = (!needmask || k0c   <= r0)
                           ? ex2(acc[nt][0]*CE - m2[0]) * invl0 : 0.f;
                float w1 = (!needmask || k0c+1 <= r0)
                           ? ex2(acc[nt][1]*CE - m2[0]) * invl0 : 0.f;
                float w2 = (!needmask || k0c   <= r1)
                           ? ex2(acc[nt][2]*CE - m2[1]) * invl1 : 0.f;
                float w3 = (!needmask || k0c+1 <= r1)
                           ? ex2(acc[nt][3]*CE - m2[1]) * invl1 : 0.f;
                ew0[nt] = pack_h2(w0, w1);
                ew1[nt] = pack_h2(w2, w3);
                if (write_w) {
                    __stcs((float2*)(wout + (basebh + r0)*SEQ + k0c),
                           make_float2(w0, w1));
                    __stcs((float2*)(wout + (basebh + r1)*SEQ + k0c),
                           make_float2(w2, w3));
                }
            }

            /* PV: w exact-f16 x vh */
#pragma unroll
            for (int t = 0; t < 4; t++) {
                uint32_t aw[4] = {ew0[2*t], ew1[2*t], ew0[2*t+1], ew1[2*t+1]};
#pragma unroll
                for (int nd = 0; nd < 4; nd++) {
                    uint32_t vh[4];
                    ldsm4t(vh[0], vh[1], vh[2], vh[3],
                           kbase + av_off + t*2304 + nd*32);
                    mma_f16(o[nd*2],   aw, vh[0], vh[1]);
                    mma_f16(o[nd*2+1], aw, vh[2], vh[3]);
                }
            }
        }

        /* write O in f16 split-A format for the out-projection */
        {
            size_t mg0 = (size_t)b*SEQ + q0 + w*16 + g;
            size_t mg1 = mg0 + 8;
#pragma unroll
            for (int nd = 0; nd < 8; nd++) {
                int col = h*64 + nd*8 + q*2;
                int blk = col >> 5, j = col & 31;
                size_t b0 = mg0*KS2 + blk*64 + j;
                size_t b1 = mg1*KS2 + blk*64 + j;
                float c0 = o[nd][0], c1 = o[nd][1];
                float c2 = o[nd][2], c3 = o[nd][3];
                __half h0 = __float2half_rn(c0);
                __half h1 = __float2half_rn(c1);
                __half h2 = __float2half_rn(c2);
                __half h3 = __float2half_rn(c3);
                *(__half2*)(s_at + b0)      = __halves2half2(h0, h1);
                *(__half2*)(s_at + b0 + 32) = __floats2half2_rn(
                    c0 - __half2float(h0), c1 - __half2float(h1));
                *(__half2*)(s_at + b1)      = __halves2half2(h2, h3);
                *(__half2*)(s_at + b1 + 32) = __floats2half2_rn(
                    c2 - __half2float(h2), c3 - __half2float(h3));
            }
        }
        __syncthreads();
    }
}

/* ---------------- launcher ---------------- */
extern "C" void kernel_launch(void* const* d_in, const int* in_sizes, int n_in,
                              void* d_out, int out_size)
{
    const float* q  = (const float*)d_in[0];
    const float* k  = (const float*)d_in[1];
    const float* v  = (const float*)d_in[2];
    const float* Wq = (const float*)d_in[3];
    const float* bq = (const float*)d_in[4];
    const float* Wk = (const float*)d_in[5];
    const float* bk = (const float*)d_in[6];
    const float* Wv = (const float*)d_in[7];
    const float* bv = (const float*)d_in[8];
    const float* Wo = (const float*)d_in[9];
    const float* bo = (const float*)d_in[10];

    float* out  = (float*)d_out;
    int write_w = (out_size >= OUT_ELEMS + W_ELEMS) ? 1 : 0;
    float* wout = out + OUT_ELEMS;

    split_all<<<33024, 256>>>(q, k, v, Wq, Wk, Wv, Wo);

    cudaFuncSetAttribute(gemm_qkv,
                         cudaFuncAttributeMaxDynamicSharedMemorySize, 2*GSTG);
    cudaFuncSetAttribute(gemm_out,
                         cudaFuncAttributeMaxDynamicSharedMemorySize, 2*GSTG);
    cudaFuncSetAttribute(attn_mma,
                         cudaFuncAttributeMaxDynamicSharedMemorySize, ASMEM);

    gemm_qkv<<<dim3(HID/128, MTOT/128, 3), 256, 2*GSTG>>>(bq, bk, bv);

    attn_mma<<<dim3(8, NH, BATCH), 256, ASMEM>>>(wout, write_w);

    gemm_out<<<dim3(HID/128, MTOT/128), 256, 2*GSTG>>>(bo, out, wout, write_w);
}

// round 16
// speedup vs baseline: 1.2614x; 1.0528x over previous
#include <cuda_runtime.h>
#include <cuda_bf16.h>
#include <cuda_fp16.h>
#include <math.h>
#include <stdint.h>

#define BATCH 2
#define SEQ   2048
#define HID   1024
#define NH    16
#define HD    64
#define MTOT  (BATCH*SEQ)
#define OUT_ELEMS   (MTOT*HID)
#define W_ELEMS     (BATCH*NH*SEQ*SEQ)
#define KS2   2048               /* f16 split-K: [hi(32) | lo(32)] x 1024 */
#define LOG2E 1.44269504088896340736f

/* ---------------- scratch (no allocations allowed) ---------------- */
__device__ float g_cos[SEQ*(HD/2)];
__device__ float g_sin[SEQ*(HD/2)];

__device__ __half g_Qh[BATCH*NH*SEQ*HD];
__device__ __half g_Ql[BATCH*NH*SEQ*HD];
__device__ __half g_Kh[BATCH*NH*SEQ*HD];
__device__ __half g_Vh[BATCH*NH*SEQ*HD];

__device__ __half s_q [MTOT*KS2];
__device__ __half s_k [MTOT*KS2];
__device__ __half s_v [MTOT*1024];
__device__ __half s_at[MTOT*KS2];
__device__ __half s_wq[HID*KS2];
__device__ __half s_wk[HID*KS2];
__device__ __half s_wv[HID*1024];
__device__ __half s_wo[HID*KS2];

/* ---------------- helpers ---------------- */
__device__ __forceinline__ uint32_t smem_u32(const void* p) {
    uint32_t a;
    asm("{ .reg .u64 t; cvta.to.shared.u64 t, %1; cvt.u32.u64 %0, t; }"
        : "=r"(a) : "l"(p));
    return a;
}
__device__ __forceinline__ void cp16(uint32_t s, const void* g) {
    asm volatile("cp.async.cg.shared.global [%0], [%1], 16;"
                 :: "r"(s), "l"(g));
}
#define CP_COMMIT() asm volatile("cp.async.commit_group;" ::: "memory")
#define CP_WAIT(N)  asm volatile("cp.async.wait_group %0;" :: "n"(N) : "memory")

__device__ __forceinline__ void ldsm4(uint32_t& r0, uint32_t& r1,
                                      uint32_t& r2, uint32_t& r3, uint32_t addr)
{
    asm volatile("ldmatrix.sync.aligned.m8n8.x4.shared.b16 {%0,%1,%2,%3}, [%4];"
                 : "=r"(r0), "=r"(r1), "=r"(r2), "=r"(r3) : "r"(addr));
}
__device__ __forceinline__ void ldsm4t(uint32_t& r0, uint32_t& r1,
                                       uint32_t& r2, uint32_t& r3, uint32_t addr)
{
    asm volatile("ldmatrix.sync.aligned.m8n8.x4.trans.shared.b16 {%0,%1,%2,%3}, [%4];"
                 : "=r"(r0), "=r"(r1), "=r"(r2), "=r"(r3) : "r"(addr));
}
__device__ __forceinline__ void mma_f16(float* d, const uint32_t* a,
                                        uint32_t b0, uint32_t b1)
{
    asm volatile(
        "mma.sync.aligned.m16n8k16.row.col.f32.f16.f16.f32 "
        "{%0,%1,%2,%3}, {%4,%5,%6,%7}, {%8,%9}, {%0,%1,%2,%3};"
        : "+f"(d[0]), "+f"(d[1]), "+f"(d[2]), "+f"(d[3])
        : "r"(a[0]), "r"(a[1]), "r"(a[2]), "r"(a[3]), "r"(b0), "r"(b1));
}
__device__ __forceinline__ float ex2(float x) {
    float y;
    asm("ex2.approx.ftz.f32 %0, %1;" : "=f"(y) : "f"(x));
    return y;
}
__device__ __forceinline__ uint32_t pack_h2(float x, float y) {
    __half2 t = __floats2half2_rn(x, y);
    return *(uint32_t*)&t;
}

/* ------ merged fp32 -> f16 split + RoPE tables, one launch -------- */
__global__ void __launch_bounds__(256)
split_all(const float* __restrict__ q, const float* __restrict__ k,
          const float* __restrict__ v, const float* __restrict__ Wq,
          const float* __restrict__ Wk, const float* __restrict__ Wv,
          const float* __restrict__ Wo)
{
    int bid = blockIdx.x;
    int tid = threadIdx.x;

    if (bid >= 32768) {                    /* rope tables */
        int idx = ((bid - 32768) << 8) + tid;
        int s = idx >> 5, j = idx & 31;
        double inv = exp(-((double)(2*j) / (double)HD) * log(10000.0));
        double ang = (double)s * inv;
        g_cos[idx] = (float)cos(ang);
        g_sin[idx] = (float)sin(ang);
        return;
    }

    if (bid < 16384) {                     /* q, k: A-format split */
        int t = bid >> 13;
        const float* src = t ? k : q;
        __half* dst = t ? s_k : s_q;
        int idx2 = ((bid & 8191) << 8) + tid;
        float2 x = ((const float2*)src)[idx2];
        int row = idx2 >> 9, kk = (idx2 & 511) * 2;
        int blk = kk >> 5,  j  = kk & 31;
        __half2 hi = __floats2half2_rn(x.x, x.y);
        size_t base = (size_t)row * KS2 + blk*64 + j;
        *(__half2*)(dst + base) = hi;
        *(__half2*)(dst + base + 32) = __floats2half2_rn(
            x.x - __half2float(hi.x), x.y - __half2float(hi.y));
        return;
    }
    if (bid < 24576) {                     /* v: flat f16 */
        int idx2 = ((bid - 16384) << 8) + tid;
        float2 x = ((const float2*)v)[idx2];
        *(__half2*)(s_v + (size_t)idx2*2) = __floats2half2_rn(x.x, x.y);
        return;
    }
    if (bid < 30720) {                     /* Wq, Wk, Wo: B-format */
        int r = bid - 24576;
        int t = r >> 11;
        const float* src = (t == 0) ? Wq : (t == 1) ? Wk : Wo;
        __half* dst = (t == 0) ? s_wq : (t == 1) ? s_wk : s_wo;
        int idx2 = ((r & 2047) << 8) + tid;
        float2 x = ((const float2*)src)[idx2];
        int row = idx2 >> 9, kk = (idx2 & 511) * 2;
        int blk = kk >> 5,  j  = kk & 31;
        __half2 hi = __floats2half2_rn(x.x, x.y);
        size_t base = (size_t)row * KS2 + blk*64 + j;
        *(__half2*)(dst + base)      = hi;
        *(__half2*)(dst + base + 32) = hi;
        return;
    }
    {                                      /* Wv: flat f16 */
        int idx2 = ((bid - 30720) << 8) + tid;
        float2 x = ((const float2*)Wv)[idx2];
        *(__half2*)(s_wv + (size_t)idx2*2) = __floats2half2_rn(x.x, x.y);
    }
}

/* ================= GEMM mainloop core (f16) ================= */
#define GSTG 36864

template<int KSZ>
__device__ __forceinline__ void gemm_core(
    const __half* __restrict__ A, const __half* __restrict__ B,
    char* gsm, int tid, int warp_m, int warp_n, int l,
    int m0, int n0, float acc[2][8][4])
{
    const uint32_t sb = smem_u32(gsm);
    const uint4* gA = (const uint4*)(A + (size_t)m0 * KSZ);
    const uint4* gB = (const uint4*)(B + (size_t)n0 * KSZ);

    uint32_t a_off[2], b_off[4];
#pragma unroll
    for (int mt = 0; mt < 2; mt++)
        a_off[mt] = (warp_m*32 + mt*16 + (l & 15))*144 + (l >> 4)*16;
#pragma unroll
    for (int nt = 0; nt < 4; nt++) {
        int row = warp_n*64 + nt*16 + (l & 7) + ((l >> 4) & 1) * 8;
        b_off[nt] = 18432 + row*144 + ((l >> 3) & 1)*16;
    }

    auto load_stage = [&](int stg, int it) {
        uint32_t base = sb + stg*GSTG;
#pragma unroll
        for (int u = 0; u < 4; u++) {
            int f = u*256 + tid;
            int r = f >> 3, c = f & 7;
            cp16(base + r*144 + c*16,         gA + (size_t)r*(KSZ/8) + it*8 + c);
            cp16(base + 18432 + r*144 + c*16, gB + (size_t)r*(KSZ/8) + it*8 + c);
        }
    };

    load_stage(0, 0);
    CP_COMMIT();

    for (int it = 0; it < KSZ/64; it++) {
        int cur = it & 1;
        if (it + 1 < KSZ/64) {
            load_stage(cur ^ 1, it + 1);
            CP_COMMIT();
            CP_WAIT(1);
        } else {
            CP_WAIT(0);
        }
        __syncthreads();

        uint32_t stgb = sb + cur*GSTG;
#pragma unroll
        for (int ks = 0; ks < 4; ks++) {
            uint32_t a[2][4], b[4][4];
#pragma unroll
            for (int mt = 0; mt < 2; mt++)
                ldsm4(a[mt][0], a[mt][1], a[mt][2], a[mt][3],
                      stgb + a_off[mt] + ks*32);
#pragma unroll
            for (int nt = 0; nt < 4; nt++)
                ldsm4(b[nt][0], b[nt][1], b[nt][2], b[nt][3],
                      stgb + b_off[nt] + ks*32);
#pragma unroll
            for (int mt = 0; mt < 2; mt++)
#pragma unroll
                for (int nt = 0; nt < 4; nt++) {
                    mma_f16(acc[mt][nt*2],   a[mt], b[nt][0], b[nt][1]);
                    mma_f16(acc[mt][nt*2+1], a[mt], b[nt][2], b[nt][3]);
                }
        }
        __syncthreads();
    }
}

/* ---- merged QKV projection GEMM: z = 0 (Q), 1 (K), 2 (V) ---- */
__global__ void __launch_bounds__(256, 2)
gemm_qkv(const float* __restrict__ bq, const float* __restrict__ bk,
         const float* __restrict__ bv)
{
    extern __shared__ __align__(16) char gsm[];

    const int tid = threadIdx.x;
    const int wid = tid >> 5, l = tid & 31;
    const int warp_m = wid >> 1, warp_n = wid & 1;
    const int m0 = blockIdx.y * 128;
    const int n0 = blockIdx.x * 128;
    const int z = blockIdx.z;

    const float* bias = (z == 0) ? bq : (z == 1) ? bk : bv;

    float acc[2][8][4];
#pragma unroll
    for (int i = 0; i < 2; i++)
#pragma unroll
        for (int j = 0; j < 8; j++)
#pragma unroll
            for (int p = 0; p < 4; p++) acc[i][j][p] = 0.f;

    if (z == 2)
        gemm_core<1024>(s_v, s_wv, gsm, tid, warp_m, warp_n, l, m0, n0, acc);
    else
        gemm_core<2048>((z == 0) ? s_q : s_k, (z == 0) ? s_wq : s_wk,
                        gsm, tid, warp_m, warp_n, l, m0, n0, acc);

    const int g = l >> 2, q = l & 3;
#pragma unroll
    for (int mt = 0; mt < 2; mt++) {
        int mrow0 = m0 + warp_m*32 + mt*16 + g;
#pragma unroll
        for (int nt2 = 0; nt2 < 8; nt2++) {
            int ncol = n0 + warp_n*64 + nt2*8 + q*2;
            float b0 = bias[ncol], b1 = bias[ncol+1];
            float c0 = acc[mt][nt2][0] + b0;
            float c1 = acc[mt][nt2][1] + b1;
            float c2 = acc[mt][nt2][2] + b0;
            float c3 = acc[mt][nt2][3] + b1;

            int h = ncol >> 6, d = ncol & 63;
            int bb0 = mrow0 >> 11, ss0 = mrow0 & 2047;
            int mrow1 = mrow0 + 8;
            int bb1 = mrow1 >> 11, ss1 = mrow1 & 2047;
            if (z < 2) {
                float cs0 = g_cos[ss0*32 + (d>>1)], sn0 = g_sin[ss0*32 + (d>>1)];
                float cs1 = g_cos[ss1*32 + (d>>1)], sn1 = g_sin[ss1*32 + (d>>1)];
                float t0 = c0*cs0 - c1*sn0, t1 = c0*sn0 + c1*cs0;
                float t2 = c2*cs1 - c3*sn1, t3 = c2*sn1 + c3*cs1;
                c0 = t0; c1 = t1; c2 = t2; c3 = t3;
            }
            size_t a0 = (((size_t)(bb0*NH + h)*SEQ + ss0) << 6) + d;
            size_t a1 = (((size_t)(bb1*NH + h)*SEQ + ss1) << 6) + d;
            __half h0 = __float2half_rn(c0);
            __half h1 = __float2half_rn(c1);
            __half h2 = __float2half_rn(c2);
            __half h3 = __float2half_rn(c3);
            if (z == 0) {
                *(__half2*)(g_Qh + a0) = __halves2half2(h0, h1);
                *(__half2*)(g_Qh + a1) = __halves2half2(h2, h3);
                *(__half2*)(g_Ql + a0) = __floats2half2_rn(
                    c0 - __half2float(h0), c1 - __half2float(h1));
                *(__half2*)(g_Ql + a1) = __floats2half2_rn(
                    c2 - __half2float(h2), c3 - __half2float(h3));
            } else if (z == 1) {
                *(__half2*)(g_Kh + a0) = __halves2half2(h0, h1);
                *(__half2*)(g_Kh + a1) = __halves2half2(h2, h3);
            } else {
                *(__half2*)(g_Vh + a0) = __halves2half2(h0, h1);
                *(__half2*)(g_Vh + a1) = __halves2half2(h2, h3);
            }
        }
    }
}

/* ---- output projection GEMM with interleaved zero-fill ---- */
__global__ void __launch_bounds__(256, 2)
gemm_out(const float* __restrict__ bo, float* __restrict__ dst,
         float* __restrict__ wout, int write_w)
{
    extern __shared__ __align__(16) char gsm[];

    const int tid = threadIdx.x;
    const int wid = tid >> 5, l = tid & 31;
    const int warp_m = wid >> 1, warp_n = wid & 1;
    const int m0 = blockIdx.y * 128;
    const int n0 = blockIdx.x * 128;
    const uint32_t sb = smem_u32(gsm);

    const int cpair = blockIdx.y * 8 + blockIdx.x;

    const uint4* gA = (const uint4*)(s_at + (size_t)m0 * KS2);
    const uint4* gB = (const uint4*)(s_wo + (size_t)n0 * KS2);

    float acc[2][8][4];
#pragma unroll
    for (int i = 0; i < 2; i++)
#pragma unroll
        for (int j = 0; j < 8; j++)
#pragma unroll
            for (int p = 0; p < 4; p++) acc[i][j][p] = 0.f;

    uint32_t a_off[2], b_off[4];
#pragma unroll
    for (int mt = 0; mt < 2; mt++)
        a_off[mt] = (warp_m*32 + mt*16 + (l & 15))*144 + (l >> 4)*16;
#pragma unroll
    for (int nt = 0; nt < 4; nt++) {
        int row = warp_n*64 + nt*16 + (l & 7) + ((l >> 4) & 1) * 8;
        b_off[nt] = 18432 + row*144 + ((l >> 3) & 1)*16;
    }

    auto load_stage = [&](int stg, int it) {
        uint32_t base = sb + stg*GSTG;
#pragma unroll
        for (int u = 0; u < 4; u++) {
            int f = u*256 + tid;
            int r = f >> 3, c = f & 7;
            cp16(base + r*144 + c*16,         gA + (size_t)r*256 + it*8 + c);
            cp16(base + 18432 + r*144 + c*16, gB + (size_t)r*256 + it*8 + c);
        }
    };

    load_stage(0, 0);
    CP_COMMIT();

    for (int it = 0; it < 32; it++) {
        int cur = it & 1;
        if (it + 1 < 32) {
            load_stage(cur ^ 1, it + 1);
            CP_COMMIT();
            CP_WAIT(1);
        } else {
            CP_WAIT(0);
        }
        __syncthreads();

        /* interleaved zero-fill: 4 rows per pair per iteration */
        if (write_w) {
            float4 z4 = make_float4(0.f, 0.f, 0.f, 0.f);
#pragma unroll
            for (int u = 0; u < 2; u++) {
                int p = u ? (511 - cpair) : cpair;
                int bh = p >> 4, qt = p & 15;
                int nf4 = (15 - qt) * 32;
                if (nf4 > 0) {
                    int q0 = qt * 128;
                    float* basep = wout + ((size_t)bh*SEQ + q0 + it*4)*SEQ
                                        + q0 + 128;
                    for (int r = 0; r < 4; r++) {
                        float4* rowp = (float4*)(basep + (size_t)r*SEQ);
                        for (int c4 = tid; c4 < nf4; c4 += 256)
                            __stcs(rowp + c4, z4);
                    }
                }
            }
        }

        uint32_t stgb = sb + cur*GSTG;
#pragma unroll
        for (int ks = 0; ks < 4; ks++) {
            uint32_t a[2][4], b[4][4];
#pragma unroll
            for (int mt = 0; mt < 2; mt++)
                ldsm4(a[mt][0], a[mt][1], a[mt][2], a[mt][3],
                      stgb + a_off[mt] + ks*32);
#pragma unroll
            for (int nt = 0; nt < 4; nt++)
                ldsm4(b[nt][0], b[nt][1], b[nt][2], b[nt][3],
                      stgb + b_off[nt] + ks*32);
#pragma unroll
            for (int mt = 0; mt < 2; mt++)
#pragma unroll
                for (int nt = 0; nt < 4; nt++) {
                    mma_f16(acc[mt][nt*2],   a[mt], b[nt][0], b[nt][1]);
                    mma_f16(acc[mt][nt*2+1], a[mt], b[nt][2], b[nt][3]);
                }
        }
        __syncthreads();
    }

    const int g = l >> 2, q = l & 3;
#pragma unroll
    for (int mt = 0; mt < 2; mt++) {
        int mrow0 = m0 + warp_m*32 + mt*16 + g;
#pragma unroll
        for (int nt2 = 0; nt2 < 8; nt2++) {
            int ncol = n0 + warp_n*64 + nt2*8 + q*2;
            float b0 = bo[ncol], b1 = bo[ncol+1];
            *(float2*)(dst + (size_t)mrow0    *HID + ncol) =
                make_float2(acc[mt][nt2][0] + b0, acc[mt][nt2][1] + b1);
            *(float2*)(dst + (size_t)(mrow0+8)*HID + ncol) =
                make_float2(acc[mt][nt2][2] + b0, acc[mt][nt2][3] + b1);
        }
    }
}

/* ================= two-pass attention, causal-paired, f16 =========
   Fixed-reference softmax (scores bounded -> no max tracking).
   Pass 1: 1-term QK (Qh x Kh) -> row sums l only.
   Pass 2: 2-term QK, w = exp2(s*CE)/l -> gmem + PV.                  */
#define QSZ   36864
#define ASTG  18432
#define ASMEM (QSZ + 3*ASTG)

__global__ void __launch_bounds__(256, 2)
attn_mma(float* __restrict__ wout, int write_w)
{
    extern __shared__ __align__(16) char dsm[];
    const int tid = threadIdx.x;
    const int w = tid >> 5, l = tid & 31;
    const int g = l >> 2, q = l & 3;
    const int h = blockIdx.y, b = blockIdx.z;
    const size_t basebh = (size_t)(b*NH + h) * SEQ;
    const uint32_t sb = smem_u32(dsm);
    const float CE = 0.125f * LOG2E;

    uint32_t bk_off[4];
    {
        int krow = (l & 7) + ((l >> 4) & 1) * 8;
        int kcb  = ((l >> 3) & 1) * 16;
#pragma unroll
        for (int nt = 0; nt < 4; nt++)
            bk_off[nt] = (nt*16 + krow)*144 + kcb;
    }
    const uint32_t aQh = sb + (w*16 + (l & 15))*144 + (l >> 4)*16;
    const uint32_t aQl = aQh + 18432;
    const uint32_t av_off = 9216 + (l & 15)*144 + (l >> 4)*16;

    auto loadK = [&](int stg, int kb) {
        uint32_t base = sb + QSZ + stg*ASTG;
        const uint4* gkh = (const uint4*)(g_Kh + (basebh + kb*64) * HD);
#pragma unroll
        for (int u = 0; u < 2; u++) {
            int f = u*256 + tid;
            int r = f >> 3, c = f & 7;
            cp16(base + r*144 + c*16, gkh + r*8 + c);
        }
    };
    auto loadKV = [&](int stg, int kb) {
        uint32_t base = sb + QSZ + stg*ASTG;
        const uint4* gkh = (const uint4*)(g_Kh + (basebh + kb*64) * HD);
        const uint4* gvh = (const uint4*)(g_Vh + (basebh + kb*64) * HD);
#pragma unroll
        for (int u = 0; u < 2; u++) {
            int f = u*256 + tid;
            int r = f >> 3, c = f & 7;
            cp16(base + r*144 + c*16,        gkh + r*8 + c);
            cp16(base + 9216 + r*144 + c*16, gvh + r*8 + c);
        }
    };

    /* 2-term QK (pass 2) */
    auto qk_tile2 = [&](uint32_t kbase, float acc[8][4]) {
#pragma unroll
        for (int nt = 0; nt < 8; nt++)
#pragma unroll
            for (int p = 0; p < 4; p++) acc[nt][p] = 0.f;
#pragma unroll
        for (int ks = 0; ks < 4; ks++) {
            uint32_t ah[4], al[4];
            ldsm4(ah[0], ah[1], ah[2], ah[3], aQh + ks*32);
            ldsm4(al[0], al[1], al[2], al[3], aQl + ks*32);
#pragma unroll
            for (int np = 0; np < 4; np++) {
                uint32_t kh[4];
                ldsm4(kh[0], kh[1], kh[2], kh[3], kbase + bk_off[np] + ks*32);
                mma_f16(acc[np*2],   ah, kh[0], kh[1]);
                mma_f16(acc[np*2+1], ah, kh[2], kh[3]);
                mma_f16(acc[np*2],   al, kh[0], kh[1]);
                mma_f16(acc[np*2+1], al, kh[2], kh[3]);
            }
        }
    };
    /* 1-term QK (pass 1: row sums only) */
    auto qk_tile1 = [&](uint32_t kbase, float acc[8][4]) {
#pragma unroll
        for (int nt = 0; nt < 8; nt++)
#pragma unroll
            for (int p = 0; p < 4; p++) acc[nt][p] = 0.f;
#pragma unroll
        for (int ks = 0; ks < 4; ks++) {
            uint32_t ah[4];
            ldsm4(ah[0], ah[1], ah[2], ah[3], aQh + ks*32);
#pragma unroll
            for (int np = 0; np < 4; np++) {
                uint32_t kh[4];
                ldsm4(kh[0], kh[1], kh[2], kh[3], kbase + bk_off[np] + ks*32);
                mma_f16(acc[np*2],   ah, kh[0], kh[1]);
                mma_f16(acc[np*2+1], ah, kh[2], kh[3]);
            }
        }
    };

    for (int half = 0; half < 2; half++) {
        const int qt = half ? blockIdx.x : (15 - blockIdx.x);
        const int q0 = qt * 128;
        const int nkt = 2*qt + 2;
        const int rw0 = q0 + w*16;
        const int r0 = rw0 + g, r1 = r0 + 8;

        /* Q loads */
        {
            const uint4* gh = (const uint4*)(g_Qh + (basebh + q0) * HD);
            const uint4* gl = (const uint4*)(g_Ql + (basebh + q0) * HD);
#pragma unroll
            for (int u = 0; u < 4; u++) {
                int f = u*256 + tid;
                int r = f >> 3, c = f & 7;
                cp16(sb + r*144 + c*16,         gh + r*8 + c);
                cp16(sb + 18432 + r*144 + c*16, gl + r*8 + c);
            }
            CP_COMMIT();
        }

        float l2[2] = {0.f, 0.f};

        /* ---------------- PASS 1: row sums (1-term QK) ---------- */
        loadK(0, 0);
        CP_COMMIT();
        if (nkt > 1) { loadK(1, 1); CP_COMMIT(); }

        for (int kb = 0; kb < nkt; kb++) {
            if (kb + 1 < nkt) CP_WAIT(1); else CP_WAIT(0);
            __syncthreads();
            if (kb + 2 < nkt) {
                loadK((kb + 2) % 3, kb + 2);
                CP_COMMIT();
            }

            float acc[8][4];
            qk_tile1(sb + QSZ + (kb % 3)*ASTG, acc);

            const bool needmask = (kb*64 + 63) > rw0;
            float s0 = 0.f, s1 = 0.f;
#pragma unroll
            for (int nt = 0; nt < 8; nt++) {
                int k0c = kb*64 + nt*8 + q*2;
                float e0 = (!needmask || k0c   <= r0) ? ex2(acc[nt][0]*CE) : 0.f;
                float e1 = (!needmask || k0c+1 <= r0) ? ex2(acc[nt][1]*CE) : 0.f;
                float e2 = (!needmask || k0c   <= r1) ? ex2(acc[nt][2]*CE) : 0.f;
                float e3 = (!needmask || k0c+1 <= r1) ? ex2(acc[nt][3]*CE) : 0.f;
                s0 += e0 + e1;
                s1 += e2 + e3;
            }
            s0 += __shfl_xor_sync(0xffffffffu, s0, 1);
            s0 += __shfl_xor_sync(0xffffffffu, s0, 2);
            s1 += __shfl_xor_sync(0xffffffffu, s1, 1);
            s1 += __shfl_xor_sync(0xffffffffu, s1, 2);
            l2[0] += s0;
            l2[1] += s1;
        }

        const float invl0 = 1.f / l2[0];
        const float invl1 = 1.f / l2[1];

        float o[8][4];
#pragma unroll
        for (int nd = 0; nd < 8; nd++)
#pragma unroll
            for (int p = 0; p < 4; p++) o[nd][p] = 0.f;

        /* ---------------- PASS 2: weights + O ---------------- */
        __syncthreads();
        loadKV(0, 0);
        CP_COMMIT();
        if (nkt > 1) { loadKV(1, 1); CP_COMMIT(); }

        for (int kb = 0; kb < nkt; kb++) {
            if (kb + 1 < nkt) CP_WAIT(1); else CP_WAIT(0);
            __syncthreads();
            if (kb + 2 < nkt) {
                loadKV((kb + 2) % 3, kb + 2);
                CP_COMMIT();
            }

            uint32_t kbase = sb + QSZ + (kb % 3)*ASTG;
            float acc[8][4];
            qk_tile2(kbase, acc);

            const bool needmask = (kb*64 + 63) > rw0;
            uint32_t ew0[8], ew1[8];
#pragma unroll
            for (int nt = 0; nt < 8; nt++) {
                int k0c = kb*64 + nt*8 + q*2;
                float w0 = (!needmask || k0c   <= r0)
                           ? ex2(acc[nt][0]*CE) * invl0 : 0.f;
                float w1 = (!needmask || k0c+1 <= r0)
                           ? ex2(acc[nt][1]*CE) * invl0 : 0.f;
                float w2 = (!needmask || k0c   <= r1)
                           ? ex2(acc[nt][2]*CE) * invl1 : 0.f;
                float w3 = (!needmask || k0c+1 <= r1)
                           ? ex2(acc[nt][3]*CE) * invl1 : 0.f;
                ew0[nt] = pack_h2(w0, w1);
                ew1[nt] = pack_h2(w2, w3);
                if (write_w) {
                    __stcs((float2*)(wout + (basebh + r0)*SEQ + k0c),
                           make_float2(w0, w1));
                    __stcs((float2*)(wout + (basebh + r1)*SEQ + k0c),
                           make_float2(w2, w3));
                }
            }

            /* PV: w exact-f16 x vh */
#pragma unroll
            for (int t = 0; t < 4; t++) {
                uint32_t aw[4] = {ew0[2*t], ew1[2*t], ew0[2*t+1], ew1[2*t+1]};
#pragma unroll
                for (int nd = 0; nd < 4; nd++) {
                    uint32_t vh[4];
                    ldsm4t(vh[0], vh[1], vh[2], vh[3],
                           kbase + av_off + t*2304 + nd*32);
                    mma_f16(o[nd*2],   aw, vh[0], vh[1]);
                    mma_f16(o[nd*2+1], aw, vh[2], vh[3]);
                }
            }
        }

        /* write O in f16 split-A format for the out-projection */
        {
            size_t mg0 = (size_t)b*SEQ + q0 + w*16 + g;
            size_t mg1 = mg0 + 8;
#pragma unroll
            for (int nd = 0; nd < 8; nd++) {
                int col = h*64 + nd*8 + q*2;
                int blk = col >> 5, j = col & 31;
                size_t b0 = mg0*KS2 + blk*64 + j;
                size_t b1 = mg1*KS2 + blk*64 + j;
                float c0 = o[nd][0], c1 = o[nd][1];
                float c2 = o[nd][2], c3 = o[nd][3];
                __half h0 = __float2half_rn(c0);
                __half h1 = __float2half_rn(c1);
                __half h2 = __float2half_rn(c2);
                __half h3 = __float2half_rn(c3);
                *(__half2*)(s_at + b0)      = __halves2half2(h0, h1);
                *(__half2*)(s_at + b0 + 32) = __floats2half2_rn(
                    c0 - __half2float(h0), c1 - __half2float(h1));
                *(__half2*)(s_at + b1)      = __halves2half2(h2, h3);
                *(__half2*)(s_at + b1 + 32) = __floats2half2_rn(
                    c2 - __half2float(h2), c3 - __half2float(h3));
            }
        }
        __syncthreads();
    }
}

/* ---------------- launcher ---------------- */
extern "C" void kernel_launch(void* const* d_in, const int* in_sizes, int n_in,
                              void* d_out, int out_size)
{
    const float* q  = (const float*)d_in[0];
    const float* k  = (const float*)d_in[1];
    const float* v  = (const float*)d_in[2];
    const float* Wq = (const float*)d_in[3];
    const float* bq = (const float*)d_in[4];
    const float* Wk = (const float*)d_in[5];
    const float* bk = (const float*)d_in[6];
    const float* Wv = (const float*)d_in[7];
    const float* bv = (const float*)d_in[8];
    const float* Wo = (const float*)d_in[9];
    const float* bo = (const float*)d_in[10];

    float* out  = (float*)d_out;
    int write_w = (out_size >= OUT_ELEMS + W_ELEMS) ? 1 : 0;
    float* wout = out + OUT_ELEMS;

    split_all<<<33024, 256>>>(q, k, v, Wq, Wk, Wv, Wo);

    cudaFuncSetAttribute(gemm_qkv,
                         cudaFuncAttributeMaxDynamicSharedMemorySize, 2*GSTG);
    cudaFuncSetAttribute(gemm_out,
                         cudaFuncAttributeMaxDynamicSharedMemorySize, 2*GSTG);
    cudaFuncSetAttribute(attn_mma,
                         cudaFuncAttributeMaxDynamicSharedMemorySize, ASMEM);

    gemm_qkv<<<dim3(HID/128, MTOT/128, 3), 256, 2*GSTG>>>(bq, bk, bv);

    attn_mma<<<dim3(8, NH, BATCH), 256, ASMEM>>>(wout, write_w);

    gemm_out<<<dim3(HID/128, MTOT/128), 256, 2*GSTG>>>(bo, out, wout, write_w);
}

// round 17
// speedup vs baseline: 1.3266x; 1.0517x over previous
#include <cuda_runtime.h>
#include <cuda_bf16.h>
#include <cuda_fp16.h>
#include <math.h>
#include <stdint.h>

#define BATCH 2
#define SEQ   2048
#define HID   1024
#define NH    16
#define HD    64
#define MTOT  (BATCH*SEQ)
#define OUT_ELEMS   (MTOT*HID)
#define W_ELEMS     (BATCH*NH*SEQ*SEQ)
#define KS2   2048               /* f16 split-K: [hi(32) | lo(32)] x 1024 */
#define LOG2E 1.44269504088896340736f

/* ---------------- scratch (no allocations allowed) ---------------- */
__device__ float g_cos[SEQ*(HD/2)];
__device__ float g_sin[SEQ*(HD/2)];

__device__ __half g_Qh[BATCH*NH*SEQ*HD];
__device__ __half g_Ql[BATCH*NH*SEQ*HD];
__device__ __half g_Kh[BATCH*NH*SEQ*HD];
__device__ __half g_Vh[BATCH*NH*SEQ*HD];

__device__ __half s_q [MTOT*KS2];          /* A-format [hi|lo] */
__device__ __half s_k [MTOT*1024];         /* flat f16 */
__device__ __half s_v [MTOT*1024];         /* flat f16 */
__device__ __half s_at[MTOT*KS2];          /* A-format [hi|lo] */
__device__ __half s_wq[HID*KS2];           /* B-format [hi|hi] */
__device__ __half s_wk[HID*1024];          /* flat f16 */
__device__ __half s_wv[HID*1024];          /* flat f16 */
__device__ __half s_wo[HID*KS2];           /* B-format [hi|hi] */

/* ---------------- helpers ---------------- */
__device__ __forceinline__ uint32_t smem_u32(const void* p) {
    uint32_t a;
    asm("{ .reg .u64 t; cvta.to.shared.u64 t, %1; cvt.u32.u64 %0, t; }"
        : "=r"(a) : "l"(p));
    return a;
}
__device__ __forceinline__ void cp16(uint32_t s, const void* g) {
    asm volatile("cp.async.cg.shared.global [%0], [%1], 16;"
                 :: "r"(s), "l"(g));
}
#define CP_COMMIT() asm volatile("cp.async.commit_group;" ::: "memory")
#define CP_WAIT(N)  asm volatile("cp.async.wait_group %0;" :: "n"(N) : "memory")

__device__ __forceinline__ void ldsm4(uint32_t& r0, uint32_t& r1,
                                      uint32_t& r2, uint32_t& r3, uint32_t addr)
{
    asm volatile("ldmatrix.sync.aligned.m8n8.x4.shared.b16 {%0,%1,%2,%3}, [%4];"
                 : "=r"(r0), "=r"(r1), "=r"(r2), "=r"(r3) : "r"(addr));
}
__device__ __forceinline__ void ldsm4t(uint32_t& r0, uint32_t& r1,
                                       uint32_t& r2, uint32_t& r3, uint32_t addr)
{
    asm volatile("ldmatrix.sync.aligned.m8n8.x4.trans.shared.b16 {%0,%1,%2,%3}, [%4];"
                 : "=r"(r0), "=r"(r1), "=r"(r2), "=r"(r3) : "r"(addr));
}
__device__ __forceinline__ void mma_f16(float* d, const uint32_t* a,
                                        uint32_t b0, uint32_t b1)
{
    asm volatile(
        "mma.sync.aligned.m16n8k16.row.col.f32.f16.f16.f32 "
        "{%0,%1,%2,%3}, {%4,%5,%6,%7}, {%8,%9}, {%0,%1,%2,%3};"
        : "+f"(d[0]), "+f"(d[1]), "+f"(d[2]), "+f"(d[3])
        : "r"(a[0]), "r"(a[1]), "r"(a[2]), "r"(a[3]), "r"(b0), "r"(b1));
}
__device__ __forceinline__ float ex2(float x) {
    float y;
    asm("ex2.approx.ftz.f32 %0, %1;" : "=f"(y) : "f"(x));
    return y;
}
__device__ __forceinline__ uint32_t pack_h2(float x, float y) {
    __half2 t = __floats2half2_rn(x, y);
    return *(uint32_t*)&t;
}

/* ------ merged fp32 -> f16 split + RoPE tables, one launch --------
   [0,8192)       q  -> s_q  A-format
   [8192,16384)   k  -> s_k  flat f16
   [16384,24576)  v  -> s_v  flat f16
   [24576,26624)  Wq -> s_wq B-format
   [26624,28672)  Wo -> s_wo B-format
   [28672,30720)  Wk -> s_wk flat f16
   [30720,32768)  Wv -> s_wv flat f16
   [32768,33024)  rope tables                                         */
__global__ void __launch_bounds__(256)
split_all(const float* __restrict__ q, const float* __restrict__ k,
          const float* __restrict__ v, const float* __restrict__ Wq,
          const float* __restrict__ Wk, const float* __restrict__ Wv,
          const float* __restrict__ Wo)
{
    int bid = blockIdx.x;
    int tid = threadIdx.x;

    if (bid >= 32768) {                    /* rope tables */
        int idx = ((bid - 32768) << 8) + tid;
        int s = idx >> 5, j = idx & 31;
        double inv = exp(-((double)(2*j) / (double)HD) * log(10000.0));
        double ang = (double)s * inv;
        g_cos[idx] = (float)cos(ang);
        g_sin[idx] = (float)sin(ang);
        return;
    }

    if (bid < 8192) {                      /* q: A-format split */
        int idx2 = (bid << 8) + tid;
        float2 x = ((const float2*)q)[idx2];
        int row = idx2 >> 9, kk = (idx2 & 511) * 2;
        int blk = kk >> 5,  j  = kk & 31;
        __half2 hi = __floats2half2_rn(x.x, x.y);
        size_t base = (size_t)row * KS2 + blk*64 + j;
        *(__half2*)(s_q + base) = hi;
        *(__half2*)(s_q + base + 32) = __floats2half2_rn(
            x.x - __half2float(hi.x), x.y - __half2float(hi.y));
        return;
    }
    if (bid < 24576) {                     /* k, v: flat f16 */
        int t = (bid - 8192) >> 13;
        const float* src = t ? v : k;
        __half* dst = t ? s_v : s_k;
        int idx2 = (((bid - 8192) & 8191) << 8) + tid;
        float2 x = ((const float2*)src)[idx2];
        *(__half2*)(dst + (size_t)idx2*2) = __floats2half2_rn(x.x, x.y);
        return;
    }
    if (bid < 28672) {                     /* Wq, Wo: B-format */
        int r = bid - 24576;
        int t = r >> 11;
        const float* src = t ? Wo : Wq;
        __half* dst = t ? s_wo : s_wq;
        int idx2 = ((r & 2047) << 8) + tid;
        float2 x = ((const float2*)src)[idx2];
        int row = idx2 >> 9, kk = (idx2 & 511) * 2;
        int blk = kk >> 5,  j  = kk & 31;
        __half2 hi = __floats2half2_rn(x.x, x.y);
        size_t base = (size_t)row * KS2 + blk*64 + j;
        *(__half2*)(dst + base)      = hi;
        *(__half2*)(dst + base + 32) = hi;
        return;
    }
    {                                      /* Wk, Wv: flat f16 */
        int r = bid - 28672;
        int t = r >> 11;
        const float* src = t ? Wv : Wk;
        __half* dst = t ? s_wv : s_wk;
        int idx2 = ((r & 2047) << 8) + tid;
        float2 x = ((const float2*)src)[idx2];
        *(__half2*)(dst + (size_t)idx2*2) = __floats2half2_rn(x.x, x.y);
    }
}

/* ================= GEMM mainloop core (f16) ================= */
#define GSTG 36864

template<int KSZ>
__device__ __forceinline__ void gemm_core(
    const __half* __restrict__ A, const __half* __restrict__ B,
    char* gsm, int tid, int warp_m, int warp_n, int l,
    int m0, int n0, float acc[2][8][4])
{
    const uint32_t sb = smem_u32(gsm);
    const uint4* gA = (const uint4*)(A + (size_t)m0 * KSZ);
    const uint4* gB = (const uint4*)(B + (size_t)n0 * KSZ);

    uint32_t a_off[2], b_off[4];
#pragma unroll
    for (int mt = 0; mt < 2; mt++)
        a_off[mt] = (warp_m*32 + mt*16 + (l & 15))*144 + (l >> 4)*16;
#pragma unroll
    for (int nt = 0; nt < 4; nt++) {
        int row = warp_n*64 + nt*16 + (l & 7) + ((l >> 4) & 1) * 8;
        b_off[nt] = 18432 + row*144 + ((l >> 3) & 1)*16;
    }

    auto load_stage = [&](int stg, int it) {
        uint32_t base = sb + stg*GSTG;
#pragma unroll
        for (int u = 0; u < 4; u++) {
            int f = u*256 + tid;
            int r = f >> 3, c = f & 7;
            cp16(base + r*144 + c*16,         gA + (size_t)r*(KSZ/8) + it*8 + c);
            cp16(base + 18432 + r*144 + c*16, gB + (size_t)r*(KSZ/8) + it*8 + c);
        }
    };

    load_stage(0, 0);
    CP_COMMIT();

    for (int it = 0; it < KSZ/64; it++) {
        int cur = it & 1;
        if (it + 1 < KSZ/64) {
            load_stage(cur ^ 1, it + 1);
            CP_COMMIT();
            CP_WAIT(1);
        } else {
            CP_WAIT(0);
        }
        __syncthreads();

        uint32_t stgb = sb + cur*GSTG;
#pragma unroll
        for (int ks = 0; ks < 4; ks++) {
            uint32_t a[2][4], b[4][4];
#pragma unroll
            for (int mt = 0; mt < 2; mt++)
                ldsm4(a[mt][0], a[mt][1], a[mt][2], a[mt][3],
                      stgb + a_off[mt] + ks*32);
#pragma unroll
            for (int nt = 0; nt < 4; nt++)
                ldsm4(b[nt][0], b[nt][1], b[nt][2], b[nt][3],
                      stgb + b_off[nt] + ks*32);
#pragma unroll
            for (int mt = 0; mt < 2; mt++)
#pragma unroll
                for (int nt = 0; nt < 4; nt++) {
                    mma_f16(acc[mt][nt*2],   a[mt], b[nt][0], b[nt][1]);
                    mma_f16(acc[mt][nt*2+1], a[mt], b[nt][2], b[nt][3]);
                }
        }
        __syncthreads();
    }
}

/* ---- merged QKV projection GEMM: z = 0 (Q), 1 (K), 2 (V) ---- */
__global__ void __launch_bounds__(256, 2)
gemm_qkv(const float* __restrict__ bq, const float* __restrict__ bk,
         const float* __restrict__ bv)
{
    extern __shared__ __align__(16) char gsm[];

    const int tid = threadIdx.x;
    const int wid = tid >> 5, l = tid & 31;
    const int warp_m = wid >> 1, warp_n = wid & 1;
    const int m0 = blockIdx.y * 128;
    const int n0 = blockIdx.x * 128;
    const int z = blockIdx.z;

    const float* bias = (z == 0) ? bq : (z == 1) ? bk : bv;

    float acc[2][8][4];
#pragma unroll
    for (int i = 0; i < 2; i++)
#pragma unroll
        for (int j = 0; j < 8; j++)
#pragma unroll
            for (int p = 0; p < 4; p++) acc[i][j][p] = 0.f;

    if (z == 0)
        gemm_core<2048>(s_q, s_wq, gsm, tid, warp_m, warp_n, l, m0, n0, acc);
    else if (z == 1)
        gemm_core<1024>(s_k, s_wk, gsm, tid, warp_m, warp_n, l, m0, n0, acc);
    else
        gemm_core<1024>(s_v, s_wv, gsm, tid, warp_m, warp_n, l, m0, n0, acc);

    const int g = l >> 2, q = l & 3;
#pragma unroll
    for (int mt = 0; mt < 2; mt++) {
        int mrow0 = m0 + warp_m*32 + mt*16 + g;
#pragma unroll
        for (int nt2 = 0; nt2 < 8; nt2++) {
            int ncol = n0 + warp_n*64 + nt2*8 + q*2;
            float b0 = bias[ncol], b1 = bias[ncol+1];
            float c0 = acc[mt][nt2][0] + b0;
            float c1 = acc[mt][nt2][1] + b1;
            float c2 = acc[mt][nt2][2] + b0;
            float c3 = acc[mt][nt2][3] + b1;

            int h = ncol >> 6, d = ncol & 63;
            int bb0 = mrow0 >> 11, ss0 = mrow0 & 2047;
            int mrow1 = mrow0 + 8;
            int bb1 = mrow1 >> 11, ss1 = mrow1 & 2047;
            if (z < 2) {
                float cs0 = g_cos[ss0*32 + (d>>1)], sn0 = g_sin[ss0*32 + (d>>1)];
                float cs1 = g_cos[ss1*32 + (d>>1)], sn1 = g_sin[ss1*32 + (d>>1)];
                float t0 = c0*cs0 - c1*sn0, t1 = c0*sn0 + c1*cs0;
                float t2 = c2*cs1 - c3*sn1, t3 = c2*sn1 + c3*cs1;
                c0 = t0; c1 = t1; c2 = t2; c3 = t3;
            }
            size_t a0 = (((size_t)(bb0*NH + h)*SEQ + ss0) << 6) + d;
            size_t a1 = (((size_t)(bb1*NH + h)*SEQ + ss1) << 6) + d;
            __half h0 = __float2half_rn(c0);
            __half h1 = __float2half_rn(c1);
            __half h2 = __float2half_rn(c2);
            __half h3 = __float2half_rn(c3);
            if (z == 0) {
                *(__half2*)(g_Qh + a0) = __halves2half2(h0, h1);
                *(__half2*)(g_Qh + a1) = __halves2half2(h2, h3);
                *(__half2*)(g_Ql + a0) = __floats2half2_rn(
                    c0 - __half2float(h0), c1 - __half2float(h1));
                *(__half2*)(g_Ql + a1) = __floats2half2_rn(
                    c2 - __half2float(h2), c3 - __half2float(h3));
            } else if (z == 1) {
                *(__half2*)(g_Kh + a0) = __halves2half2(h0, h1);
                *(__half2*)(g_Kh + a1) = __halves2half2(h2, h3);
            } else {
                *(__half2*)(g_Vh + a0) = __halves2half2(h0, h1);
                *(__half2*)(g_Vh + a1) = __halves2half2(h2, h3);
            }
        }
    }
}

/* ---- output projection GEMM with interleaved zero-fill ---- */
__global__ void __launch_bounds__(256, 2)
gemm_out(const float* __restrict__ bo, float* __restrict__ dst,
         float* __restrict__ wout, int write_w)
{
    extern __shared__ __align__(16) char gsm[];

    const int tid = threadIdx.x;
    const int wid = tid >> 5, l = tid & 31;
    const int warp_m = wid >> 1, warp_n = wid & 1;
    const int m0 = blockIdx.y * 128;
    const int n0 = blockIdx.x * 128;
    const uint32_t sb = smem_u32(gsm);

    const int cpair = blockIdx.y * 8 + blockIdx.x;

    const uint4* gA = (const uint4*)(s_at + (size_t)m0 * KS2);
    const uint4* gB = (const uint4*)(s_wo + (size_t)n0 * KS2);

    float acc[2][8][4];
#pragma unroll
    for (int i = 0; i < 2; i++)
#pragma unroll
        for (int j = 0; j < 8; j++)
#pragma unroll
            for (int p = 0; p < 4; p++) acc[i][j][p] = 0.f;

    uint32_t a_off[2], b_off[4];
#pragma unroll
    for (int mt = 0; mt < 2; mt++)
        a_off[mt] = (warp_m*32 + mt*16 + (l & 15))*144 + (l >> 4)*16;
#pragma unroll
    for (int nt = 0; nt < 4; nt++) {
        int row = warp_n*64 + nt*16 + (l & 7) + ((l >> 4) & 1) * 8;
        b_off[nt] = 18432 + row*144 + ((l >> 3) & 1)*16;
    }

    auto load_stage = [&](int stg, int it) {
        uint32_t base = sb + stg*GSTG;
#pragma unroll
        for (int u = 0; u < 4; u++) {
            int f = u*256 + tid;
            int r = f >> 3, c = f & 7;
            cp16(base + r*144 + c*16,         gA + (size_t)r*256 + it*8 + c);
            cp16(base + 18432 + r*144 + c*16, gB + (size_t)r*256 + it*8 + c);
        }
    };

    load_stage(0, 0);
    CP_COMMIT();

    for (int it = 0; it < 32; it++) {
        int cur = it & 1;
        if (it + 1 < 32) {
            load_stage(cur ^ 1, it + 1);
            CP_COMMIT();
            CP_WAIT(1);
        } else {
            CP_WAIT(0);
        }
        __syncthreads();

        /* interleaved zero-fill: 4 rows per pair per iteration */
        if (write_w) {
            float4 z4 = make_float4(0.f, 0.f, 0.f, 0.f);
#pragma unroll
            for (int u = 0; u < 2; u++) {
                int p = u ? (511 - cpair) : cpair;
                int bh = p >> 4, qt = p & 15;
                int nf4 = (15 - qt) * 32;
                if (nf4 > 0) {
                    int q0 = qt * 128;
                    float* basep = wout + ((size_t)bh*SEQ + q0 + it*4)*SEQ
                                        + q0 + 128;
                    for (int r = 0; r < 4; r++) {
                        float4* rowp = (float4*)(basep + (size_t)r*SEQ);
                        for (int c4 = tid; c4 < nf4; c4 += 256)
                            __stcs(rowp + c4, z4);
                    }
                }
            }
        }

        uint32_t stgb = sb + cur*GSTG;
#pragma unroll
        for (int ks = 0; ks < 4; ks++) {
            uint32_t a[2][4], b[4][4];
#pragma unroll
            for (int mt = 0; mt < 2; mt++)
                ldsm4(a[mt][0], a[mt][1], a[mt][2], a[mt][3],
                      stgb + a_off[mt] + ks*32);
#pragma unroll
            for (int nt = 0; nt < 4; nt++)
                ldsm4(b[nt][0], b[nt][1], b[nt][2], b[nt][3],
                      stgb + b_off[nt] + ks*32);
#pragma unroll
            for (int mt = 0; mt < 2; mt++)
#pragma unroll
                for (int nt = 0; nt < 4; nt++) {
                    mma_f16(acc[mt][nt*2],   a[mt], b[nt][0], b[nt][1]);
                    mma_f16(acc[mt][nt*2+1], a[mt], b[nt][2], b[nt][3]);
                }
        }
        __syncthreads();
    }

    const int g = l >> 2, q = l & 3;
#pragma unroll
    for (int mt = 0; mt < 2; mt++) {
        int mrow0 = m0 + warp_m*32 + mt*16 + g;
#pragma unroll
        for (int nt2 = 0; nt2 < 8; nt2++) {
            int ncol = n0 + warp_n*64 + nt2*8 + q*2;
            float b0 = bo[ncol], b1 = bo[ncol+1];
            *(float2*)(dst + (size_t)mrow0    *HID + ncol) =
                make_float2(acc[mt][nt2][0] + b0, acc[mt][nt2][1] + b1);
            *(float2*)(dst + (size_t)(mrow0+8)*HID + ncol) =
                make_float2(acc[mt][nt2][2] + b0, acc[mt][nt2][3] + b1);
        }
    }
}

/* ================= two-pass attention, causal-paired, f16 =========
   Fixed-reference softmax. Pass 1: 1-term QK -> row sums.
   Pass 2: 2-term QK, w = exp2(s*CE)/l -> gmem + PV.                  */
#define QSZ   36864
#define ASTG  18432
#define ASMEM (QSZ + 3*ASTG)

__global__ void __launch_bounds__(256, 2)
attn_mma(float* __restrict__ wout, int write_w)
{
    extern __shared__ __align__(16) char dsm[];
    const int tid = threadIdx.x;
    const int w = tid >> 5, l = tid & 31;
    const int g = l >> 2, q = l & 3;
    const int h = blockIdx.y, b = blockIdx.z;
    const size_t basebh = (size_t)(b*NH + h) * SEQ;
    const uint32_t sb = smem_u32(dsm);
    const float CE = 0.125f * LOG2E;

    uint32_t bk_off[4];
    {
        int krow = (l & 7) + ((l >> 4) & 1) * 8;
        int kcb  = ((l >> 3) & 1) * 16;
#pragma unroll
        for (int nt = 0; nt < 4; nt++)
            bk_off[nt] = (nt*16 + krow)*144 + kcb;
    }
    const uint32_t aQh = sb + (w*16 + (l & 15))*144 + (l >> 4)*16;
    const uint32_t aQl = aQh + 18432;
    const uint32_t av_off = 9216 + (l & 15)*144 + (l >> 4)*16;

    auto loadK = [&](int stg, int kb) {
        uint32_t base = sb + QSZ + stg*ASTG;
        const uint4* gkh = (const uint4*)(g_Kh + (basebh + kb*64) * HD);
#pragma unroll
        for (int u = 0; u < 2; u++) {
            int f = u*256 + tid;
            int r = f >> 3, c = f & 7;
            cp16(base + r*144 + c*16, gkh + r*8 + c);
        }
    };
    auto loadKV = [&](int stg, int kb) {
        uint32_t base = sb + QSZ + stg*ASTG;
        const uint4* gkh = (const uint4*)(g_Kh + (basebh + kb*64) * HD);
        const uint4* gvh = (const uint4*)(g_Vh + (basebh + kb*64) * HD);
#pragma unroll
        for (int u = 0; u < 2; u++) {
            int f = u*256 + tid;
            int r = f >> 3, c = f & 7;
            cp16(base + r*144 + c*16,        gkh + r*8 + c);
            cp16(base + 9216 + r*144 + c*16, gvh + r*8 + c);
        }
    };

    auto qk_tile2 = [&](uint32_t kbase, float acc[8][4]) {
#pragma unroll
        for (int nt = 0; nt < 8; nt++)
#pragma unroll
            for (int p = 0; p < 4; p++) acc[nt][p] = 0.f;
#pragma unroll
        for (int ks = 0; ks < 4; ks++) {
            uint32_t ah[4], al[4];
            ldsm4(ah[0], ah[1], ah[2], ah[3], aQh + ks*32);
            ldsm4(al[0], al[1], al[2], al[3], aQl + ks*32);
#pragma unroll
            for (int np = 0; np < 4; np++) {
                uint32_t kh[4];
                ldsm4(kh[0], kh[1], kh[2], kh[3], kbase + bk_off[np] + ks*32);
                mma_f16(acc[np*2],   ah, kh[0], kh[1]);
                mma_f16(acc[np*2+1], ah, kh[2], kh[3]);
                mma_f16(acc[np*2],   al, kh[0], kh[1]);
                mma_f16(acc[np*2+1], al, kh[2], kh[3]);
            }
        }
    };
    auto qk_tile1 = [&](uint32_t kbase, float acc[8][4]) {
#pragma unroll
        for (int nt = 0; nt < 8; nt++)
#pragma unroll
            for (int p = 0; p < 4; p++) acc[nt][p] = 0.f;
#pragma unroll
        for (int ks = 0; ks < 4; ks++) {
            uint32_t ah[4];
            ldsm4(ah[0], ah[1], ah[2], ah[3], aQh + ks*32);
#pragma unroll
            for (int np = 0; np < 4; np++) {
                uint32_t kh[4];
                ldsm4(kh[0], kh[1], kh[2], kh[3], kbase + bk_off[np] + ks*32);
                mma_f16(acc[np*2],   ah, kh[0], kh[1]);
                mma_f16(acc[np*2+1], ah, kh[2], kh[3]);
            }
        }
    };

    for (int half = 0; half < 2; half++) {
        const int qt = half ? blockIdx.x : (15 - blockIdx.x);
        const int q0 = qt * 128;
        const int nkt = 2*qt + 2;
        const int rw0 = q0 + w*16;
        const int r0 = rw0 + g, r1 = r0 + 8;

        /* Q loads */
        {
            const uint4* gh = (const uint4*)(g_Qh + (basebh + q0) * HD);
            const uint4* gl = (const uint4*)(g_Ql + (basebh + q0) * HD);
#pragma unroll
            for (int u = 0; u < 4; u++) {
                int f = u*256 + tid;
                int r = f >> 3, c = f & 7;
                cp16(sb + r*144 + c*16,         gh + r*8 + c);
                cp16(sb + 18432 + r*144 + c*16, gl + r*8 + c);
            }
            CP_COMMIT();
        }

        float l2[2] = {0.f, 0.f};

        /* ---------------- PASS 1: row sums (1-term QK) ---------- */
        loadK(0, 0);
        CP_COMMIT();
        if (nkt > 1) { loadK(1, 1); CP_COMMIT(); }

        for (int kb = 0; kb < nkt; kb++) {
            if (kb + 1 < nkt) CP_WAIT(1); else CP_WAIT(0);
            __syncthreads();
            if (kb + 2 < nkt) {
                loadK((kb + 2) % 3, kb + 2);
                CP_COMMIT();
            }

            float acc[8][4];
            qk_tile1(sb + QSZ + (kb % 3)*ASTG, acc);

            const bool needmask = (kb*64 + 63) > rw0;
            float s0 = 0.f, s1 = 0.f;
#pragma unroll
            for (int nt = 0; nt < 8; nt++) {
                int k0c = kb*64 + nt*8 + q*2;
                float e0 = (!needmask || k0c   <= r0) ? ex2(acc[nt][0]*CE) : 0.f;
                float e1 = (!needmask || k0c+1 <= r0) ? ex2(acc[nt][1]*CE) : 0.f;
                float e2 = (!needmask || k0c   <= r1) ? ex2(acc[nt][2]*CE) : 0.f;
                float e3 = (!needmask || k0c+1 <= r1) ? ex2(acc[nt][3]*CE) : 0.f;
                s0 += e0 + e1;
                s1 += e2 + e3;
            }
            s0 += __shfl_xor_sync(0xffffffffu, s0, 1);
            s0 += __shfl_xor_sync(0xffffffffu, s0, 2);
            s1 += __shfl_xor_sync(0xffffffffu, s1, 1);
            s1 += __shfl_xor_sync(0xffffffffu, s1, 2);
            l2[0] += s0;
            l2[1] += s1;
        }

        const float invl0 = 1.f / l2[0];
        const float invl1 = 1.f / l2[1];

        float o[8][4];
#pragma unroll
        for (int nd = 0; nd < 8; nd++)
#pragma unroll
            for (int p = 0; p < 4; p++) o[nd][p] = 0.f;

        /* ---------------- PASS 2: weights + O ---------------- */
        __syncthreads();
        loadKV(0, 0);
        CP_COMMIT();
        if (nkt > 1) { loadKV(1, 1); CP_COMMIT(); }

        for (int kb = 0; kb < nkt; kb++) {
            if (kb + 1 < nkt) CP_WAIT(1); else CP_WAIT(0);
            __syncthreads();
            if (kb + 2 < nkt) {
                loadKV((kb + 2) % 3, kb + 2);
                CP_COMMIT();
            }

            uint32_t kbase = sb + QSZ + (kb % 3)*ASTG;
            float acc[8][4];
            qk_tile2(kbase, acc);

            const bool needmask = (kb*64 + 63) > rw0;
            uint32_t ew0[8], ew1[8];
#pragma unroll
            for (int nt = 0; nt < 8; nt++) {
                int k0c = kb*64 + nt*8 + q*2;
                float w0 = (!needmask || k0c   <= r0)
                           ? ex2(acc[nt][0]*CE) * invl0 : 0.f;
                float w1 = (!needmask || k0c+1 <= r0)
                           ? ex2(acc[nt][1]*CE) * invl0 : 0.f;
                float w2 = (!needmask || k0c   <= r1)
                           ? ex2(acc[nt][2]*CE) * invl1 : 0.f;
                float w3 = (!needmask || k0c+1 <= r1)
                           ? ex2(acc[nt][3]*CE) * invl1 : 0.f;
                ew0[nt] = pack_h2(w0, w1);
                ew1[nt] = pack_h2(w2, w3);
                if (write_w) {
                    __stcs((float2*)(wout + (basebh + r0)*SEQ + k0c),
                           make_float2(w0, w1));
                    __stcs((float2*)(wout + (basebh + r1)*SEQ + k0c),
                           make_float2(w2, w3));
                }
            }

            /* PV: w exact-f16 x vh */
#pragma unroll
            for (int t = 0; t < 4; t++) {
                uint32_t aw[4] = {ew0[2*t], ew1[2*t], ew0[2*t+1], ew1[2*t+1]};
#pragma unroll
                for (int nd = 0; nd < 4; nd++) {
                    uint32_t vh[4];
                    ldsm4t(vh[0], vh[1], vh[2], vh[3],
                           kbase + av_off + t*2304 + nd*32);
                    mma_f16(o[nd*2],   aw, vh[0], vh[1]);
                    mma_f16(o[nd*2+1], aw, vh[2], vh[3]);
                }
            }
        }

        /* write O in f16 split-A format for the out-projection */
        {
            size_t mg0 = (size_t)b*SEQ + q0 + w*16 + g;
            size_t mg1 = mg0 + 8;
#pragma unroll
            for (int nd = 0; nd < 8; nd++) {
                int col = h*64 + nd*8 + q*2;
                int blk = col >> 5, j = col & 31;
                size_t b0 = mg0*KS2 + blk*64 + j;
                size_t b1 = mg1*KS2 + blk*64 + j;
                float c0 = o[nd][0], c1 = o[nd][1];
                float c2 = o[nd][2], c3 = o[nd][3];
                __half h0 = __float2half_rn(c0);
                __half h1 = __float2half_rn(c1);
                __half h2 = __float2half_rn(c2);
                __half h3 = __float2half_rn(c3);
                *(__half2*)(s_at + b0)      = __halves2half2(h0, h1);
                *(__half2*)(s_at + b0 + 32) = __floats2half2_rn(
                    c0 - __half2float(h0), c1 - __half2float(h1));
                *(__half2*)(s_at + b1)      = __halves2half2(h2, h3);
                *(__half2*)(s_at + b1 + 32) = __floats2half2_rn(
                    c2 - __half2float(h2), c3 - __half2float(h3));
            }
        }
        __syncthreads();
    }
}

/* ---------------- launcher ---------------- */
extern "C" void kernel_launch(void* const* d_in, const int* in_sizes, int n_in,
                              void* d_out, int out_size)
{
    const float* q  = (const float*)d_in[0];
    const float* k  = (const float*)d_in[1];
    const float* v  = (const float*)d_in[2];
    const float* Wq = (const float*)d_in[3];
    const float* bq = (const float*)d_in[4];
    const float* Wk = (const float*)d_in[5];
    const float* bk = (const float*)d_in[6];
    const float* Wv = (const float*)d_in[7];
    const float* bv = (const float*)d_in[8];
    const float* Wo = (const float*)d_in[9];
    const float* bo = (const float*)d_in[10];

    float* out  = (float*)d_out;
    int write_w = (out_size >= OUT_ELEMS + W_ELEMS) ? 1 : 0;
    float* wout = out + OUT_ELEMS;

    split_all<<<33024, 256>>>(q, k, v, Wq, Wk, Wv, Wo);

    cudaFuncSetAttribute(gemm_qkv,
                         cudaFuncAttributeMaxDynamicSharedMemorySize, 2*GSTG);
    cudaFuncSetAttribute(gemm_out,
                         cudaFuncAttributeMaxDynamicSharedMemorySize, 2*GSTG);
    cudaFuncSetAttribute(attn_mma,
                         cudaFuncAttributeMaxDynamicSharedMemorySize, ASMEM);

    gemm_qkv<<<dim3(HID/128, MTOT/128, 3), 256, 2*GSTG>>>(bq, bk, bv);

    attn_mma<<<dim3(8, NH, BATCH), 256, ASMEM>>>(wout, write_w);

    gemm_out<<<dim3(HID/128, MTOT/128), 256, 2*GSTG>>>(bo, out, wout, write_w);
}